// round 13
// baseline (speedup 1.0000x reference)
#include <cuda_runtime.h>
#include <cuda_fp16.h>
#include <math.h>

// Problem constants
#define B_  256
#define T_  128
#define E_  300
#define H_  512
#define G4  2048          // 4*H
#define F_  1024
#define NL  4
#define BT  32768         // B*T
#define KP_ 304           // E padded to 16
#define KT_PRE 19         // 304/16
#define KT2  16           // recurrent: 16 stages of K=32
#define NSTAGE 4

// ---------------------------------------------------------------------------
// Device scratch (static; no allocations anywhere)
// ---------------------------------------------------------------------------
__device__ float g_pre[268435456];            // [4][B*T][G4] = 1.07 GB
__device__ float g_xt [2 * BT * KP_];         // tf32-rounded, zero-padded inputs
__device__ float g_wt [NL * KP_ * G4];        // tf32-rounded, padded input weights
__device__ float g_wh [NL * H_  * G4];        // RAW fp32 recurrent weights
__device__ __align__(256) __half g_hh[2][NL * B_ * H_];  // fp16 hidden ping-pong
__device__ float g_c  [NL * B_ * H_];         // cell state (final only)
__device__ float g_rnn[B_ * G4];              // concat of final c's
__device__ float g_act[3][B_ * F_];           // MLP activations
__device__ unsigned long long g_arrive [NL];
__device__ unsigned long long g_release[NL];

__device__ __forceinline__ float f2tf32(float x) {
    unsigned u;
    asm("cvt.rna.tf32.f32 %0, %1;" : "=r"(u) : "f"(x));
    return __uint_as_float(u);
}

// ===========================================================================
// k_zero: zero initial states (per replay)
// ===========================================================================
__global__ void k_zero()
{
    int idx = blockIdx.x * 256 + threadIdx.x;
    if (idx < NL * B_ * H_) {
        g_hh[0][idx] = __float2half(0.f);
        g_hh[1][idx] = __float2half(0.f);
    }
}

// ===========================================================================
// k_prep_all: tf32 rounding for precompute operands; raw copy of Wh.
// ===========================================================================
__global__ void k_prep_all(
    const float* __restrict__ prem, const float* __restrict__ hyp,
    const float* __restrict__ W0, const float* __restrict__ W1,
    const float* __restrict__ W2, const float* __restrict__ W3)
{
    long idx = (long)blockIdx.x * 256 + threadIdx.x;

    if (idx < 2L * BT * KP_) {
        int which = (int)(idx / ((long)BT * KP_));
        long rem  = idx - (long)which * BT * KP_;
        int row = (int)(rem / KP_), col = (int)(rem - (long)row * KP_);
        const float* x = which ? hyp : prem;
        g_xt[idx] = (col < E_) ? f2tf32(x[(long)row * E_ + col]) : 0.f;
    }
    if (idx < (long)NL * KP_ * G4) {
        int l = (int)(idx / ((long)KP_ * G4));
        long rem = idx - (long)l * KP_ * G4;
        int r = (int)(rem / G4), c = (int)(rem - (long)r * G4);
        const float* W = (l == 0) ? W0 : (l == 1) ? W1 : (l == 2) ? W2 : W3;
        g_wt[idx] = (r < E_) ? f2tf32(W[(long)r * G4 + c]) : 0.f;
    }
    if (idx < (long)NL * H_ * G4) {
        int l = (int)(idx / ((long)H_ * G4));
        long rem = idx - (long)l * H_ * G4;
        int r = (int)(rem / G4), c = (int)(rem - (long)r * G4);
        const float* W = (l == 0) ? W0 : (l == 1) ? W1 : (l == 2) ? W2 : W3;
        g_wh[idx] = W[(long)(E_ + r) * G4 + c];   // raw; fp16-rounded in-kernel
    }
}

// ===========================================================================
// Precompute GEMM (tf32, unchanged): g_pre[l] = Xt @ Wt_l + b_l
// ===========================================================================
#define PRE_A_STAGE (128 * 20)
#define PRE_B_STAGE (16 * 136)
#define PRE_SMEM_BYTES ((NSTAGE * PRE_A_STAGE + NSTAGE * PRE_B_STAGE) * 4)

__device__ __forceinline__ void pre_issue(
    unsigned sA, unsigned sB, const float* __restrict__ A,
    const float* __restrict__ Bw, int kt, long m0, long n0, int tid)
{
#pragma unroll
    for (int i = 0; i < 2; i++) {
        int c = tid + i * 256;
        int row = c >> 2, c4 = (c & 3) << 2;
        unsigned dst = sA + (unsigned)(row * 20 + c4) * 4u;
        const float* src = A + (m0 + row) * KP_ + kt * 16 + c4;
        asm volatile("cp.async.cg.shared.global [%0], [%1], 16;"
                     :: "r"(dst), "l"(src));
    }
#pragma unroll
    for (int i = 0; i < 2; i++) {
        int c = tid + i * 256;
        int row = c >> 5, c4 = (c & 31) << 2;
        unsigned dst = sB + (unsigned)(row * 136 + c4) * 4u;
        const float* src = Bw + (long)(kt * 16 + row) * G4 + n0 + c4;
        asm volatile("cp.async.cg.shared.global [%0], [%1], 16;"
                     :: "r"(dst), "l"(src));
    }
    asm volatile("cp.async.commit_group;");
}

__device__ __forceinline__ void pre_compute(
    const float* As, const float* Bs, float acc[4][4][4],
    int wr, int wc, int g, int t4)
{
#pragma unroll
    for (int ks = 0; ks < 2; ks++) {
        int k0 = ks * 8;
        unsigned af[4][4], bf[4][2];
#pragma unroll
        for (int mi = 0; mi < 4; mi++) {
            int rb = wr * 64 + mi * 16;
            af[mi][0] = __float_as_uint(As[(rb + g    ) * 20 + k0 + t4    ]);
            af[mi][1] = __float_as_uint(As[(rb + g + 8) * 20 + k0 + t4    ]);
            af[mi][2] = __float_as_uint(As[(rb + g    ) * 20 + k0 + t4 + 4]);
            af[mi][3] = __float_as_uint(As[(rb + g + 8) * 20 + k0 + t4 + 4]);
        }
#pragma unroll
        for (int ni = 0; ni < 4; ni++) {
            int cb = wc * 32 + ni * 8;
            bf[ni][0] = __float_as_uint(Bs[(k0 + t4    ) * 136 + cb + g]);
            bf[ni][1] = __float_as_uint(Bs[(k0 + t4 + 4) * 136 + cb + g]);
        }
#pragma unroll
        for (int mi = 0; mi < 4; mi++)
#pragma unroll
            for (int ni = 0; ni < 4; ni++)
                asm volatile(
                    "mma.sync.aligned.m16n8k8.row.col.f32.tf32.tf32.f32 "
                    "{%0,%1,%2,%3},{%4,%5,%6,%7},{%8,%9},{%0,%1,%2,%3};"
                    : "+f"(acc[mi][ni][0]), "+f"(acc[mi][ni][1]),
                      "+f"(acc[mi][ni][2]), "+f"(acc[mi][ni][3])
                    : "r"(af[mi][0]), "r"(af[mi][1]), "r"(af[mi][2]), "r"(af[mi][3]),
                      "r"(bf[ni][0]), "r"(bf[ni][1]));
    }
}

__global__ __launch_bounds__(256) void k_precompute2(
    const float* __restrict__ b0, const float* __restrict__ b1,
    const float* __restrict__ b2, const float* __restrict__ b3)
{
    extern __shared__ float smem[];
    float* As = smem;
    float* Bs = smem + NSTAGE * PRE_A_STAGE;
    unsigned sAb = (unsigned)__cvta_generic_to_shared(As);
    unsigned sBb = (unsigned)__cvta_generic_to_shared(Bs);

    int tid = threadIdx.x, lane = tid & 31, wid = tid >> 5;
    int wr = wid >> 2, wc = wid & 3, g = lane >> 2, t4 = lane & 3;
    int l = blockIdx.z;
    long n0 = (long)blockIdx.x * 128, m0 = (long)blockIdx.y * 128;
    const float* A  = g_xt + (long)(l >> 1) * BT * KP_;
    const float* Bw = g_wt + (long)l * KP_ * G4;
    const float* bb = (l == 0) ? b0 : (l == 1) ? b1 : (l == 2) ? b2 : b3;

    float acc[4][4][4];
#pragma unroll
    for (int mi = 0; mi < 4; mi++)
#pragma unroll
        for (int ni = 0; ni < 4; ni++)
#pragma unroll
            for (int k = 0; k < 4; k++) acc[mi][ni][k] = 0.f;

#pragma unroll
    for (int p = 0; p < NSTAGE - 1; p++)
        pre_issue(sAb + p * PRE_A_STAGE * 4, sBb + p * PRE_B_STAGE * 4,
                  A, Bw, p, m0, n0, tid);

    for (int kt = 0; kt < KT_PRE; kt++) {
        asm volatile("cp.async.wait_group %0;" :: "n"(NSTAGE - 2));
        __syncthreads();
        int stg = kt & (NSTAGE - 1);
        pre_compute(As + stg * PRE_A_STAGE, Bs + stg * PRE_B_STAGE,
                    acc, wr, wc, g, t4);
        int nk = kt + NSTAGE - 1;
        if (nk < KT_PRE)
            pre_issue(sAb + (nk & (NSTAGE - 1)) * PRE_A_STAGE * 4,
                      sBb + (nk & (NSTAGE - 1)) * PRE_B_STAGE * 4,
                      A, Bw, nk, m0, n0, tid);
        else
            asm volatile("cp.async.commit_group;");
    }

    float* out = g_pre + (long)l * BT * G4;
#pragma unroll
    for (int mi = 0; mi < 4; mi++)
#pragma unroll
        for (int ni = 0; ni < 4; ni++) {
            long col = n0 + wc * 32 + ni * 8 + t4 * 2;
            float bx = bb[col], by = bb[col + 1];
#pragma unroll
            for (int h = 0; h < 2; h++) {
                long row = m0 + wr * 64 + mi * 16 + g + h * 8;
                float2 v;
                v.x = acc[mi][ni][h * 2 + 0] + bx;
                v.y = acc[mi][ni][h * 2 + 1] + by;
                *(float2*)(out + row * G4 + col) = v;
            }
        }
}

// ===========================================================================
// Persistent recurrent kernel — 256 blocks (64/LSTM), 2 blocks/SM,
// 256 threads each. block = (l = bid>>6, nb = bid&63): 8 units x 4 gates
// (N=32), M=256, K=512. 8 warps, each = 32-row M-strip covering all 4 gates.
// Wh slice in smem (32 KB) as m16n8k16 B-fragments; h via cp.async in 16
// stages of K=32. Cell state in registers. Two co-resident blocks per SM
// give independent instruction streams to cover block-wide sync stalls.
// ===========================================================================
#define STEP_THREADS 256

struct StepSmem {
    uint2  Wfrag[128][32];           // [kt*4 + ni][lane]   32 KB
    __half As[NSTAGE][256][40];      // 32 halves + pad     80 KB
};
#define STEP_SMEM_BYTES sizeof(StepSmem)
#define AS_STAGE_BYTES (256 * 40 * 2)

__device__ __forceinline__ void issue_A32(unsigned as_base_b, const __half* hp,
                                          int s, int tid)
{
#pragma unroll
    for (int i = 0; i < 4; i++) {
        int c = tid + i * STEP_THREADS;      // 0..1023 chunks of 16B
        int row = c >> 2, ch = c & 3;
        unsigned dst = as_base_b + (unsigned)(row * 40 + ch * 8) * 2u;
        const __half* src = hp + row * 512 + s * 32 + ch * 8;
        asm volatile("cp.async.cg.shared.global [%0], [%1], 16;"
                     :: "r"(dst), "l"(src));
    }
    asm volatile("cp.async.commit_group;");
}

__device__ __forceinline__ void step_compute_stage(
    const StepSmem* s, int stg, int st, float acc[2][4][4],
    int wr, int g, int t4, int lane)
{
    const __half* As = &s->As[stg][0][0];
#pragma unroll
    for (int ks = 0; ks < 2; ks++) {
        int kh = ks * 16;
        unsigned af[2][4];
        uint2    bf[4];
#pragma unroll
        for (int mi = 0; mi < 2; mi++) {
            int r0 = (wr * 32 + mi * 16 + g) * 40;
            int r1 = r0 + 8 * 40;
            af[mi][0] = *(const unsigned*)(As + r0 + kh + 2 * t4);
            af[mi][1] = *(const unsigned*)(As + r1 + kh + 2 * t4);
            af[mi][2] = *(const unsigned*)(As + r0 + kh + 8 + 2 * t4);
            af[mi][3] = *(const unsigned*)(As + r1 + kh + 8 + 2 * t4);
        }
        int kt = st * 2 + ks;
#pragma unroll
        for (int ni = 0; ni < 4; ni++)
            bf[ni] = s->Wfrag[kt * 4 + ni][lane];
#pragma unroll
        for (int mi = 0; mi < 2; mi++)
#pragma unroll
            for (int ni = 0; ni < 4; ni++)
                asm volatile(
                    "mma.sync.aligned.m16n8k16.row.col.f32.f16.f16.f32 "
                    "{%0,%1,%2,%3},{%4,%5,%6,%7},{%8,%9},{%0,%1,%2,%3};"
                    : "+f"(acc[mi][ni][0]), "+f"(acc[mi][ni][1]),
                      "+f"(acc[mi][ni][2]), "+f"(acc[mi][ni][3])
                    : "r"(af[mi][0]), "r"(af[mi][1]), "r"(af[mi][2]), "r"(af[mi][3]),
                      "r"(bf[ni].x), "r"(bf[ni].y));
    }
}

__global__ __launch_bounds__(STEP_THREADS, 2) void k_step_persist()
{
    extern __shared__ char raw[];
    StepSmem* s = (StepSmem*)raw;
    int tid = threadIdx.x, lane = tid & 31, wid = tid >> 5;
    int wr = wid, g = lane >> 2, t4 = lane & 3;
    int bid = blockIdx.x, l = bid >> 6, nb = bid & 63;
    const float* Wh = g_wh + (long)l * H_ * G4;

    // one-time: build fp16 B-fragments in smem (m16n8k16 layout).
    // frag f = kt*4 + ni; lane -> (g = col-in-tile 0..7, t4 = k pair).
    for (int f = wid; f < 128; f += 8) {
        int kt = f >> 2, ni = f & 3;
        int col = ni * H_ + nb * 8 + g;
        int k0  = kt * 16 + 2 * t4;
        float w0 = Wh[(long)(k0    ) * G4 + col];
        float w1 = Wh[(long)(k0 + 1) * G4 + col];
        float w2 = Wh[(long)(k0 + 8) * G4 + col];
        float w3 = Wh[(long)(k0 + 9) * G4 + col];
        __half2 p0 = __floats2half2_rn(w0, w1);
        __half2 p1 = __floats2half2_rn(w2, w3);
        uint2 v;
        v.x = *(unsigned*)&p0;
        v.y = *(unsigned*)&p1;
        s->Wfrag[f][lane] = v;
    }
    __syncthreads();

    const float* pre_l = g_pre + (long)l * BT * G4;
    unsigned as0 = (unsigned)__cvta_generic_to_shared(&s->As[0][0][0]);
    int u0 = nb * 8 + t4 * 2;

    // cell state in registers for the whole time loop
    float creg[2][2][2];
#pragma unroll
    for (int mi = 0; mi < 2; mi++)
#pragma unroll
        for (int hh = 0; hh < 2; hh++) {
            creg[mi][hh][0] = 0.f;
            creg[mi][hh][1] = 0.f;
        }

    for (int t = 0; t < T_; t++) {
        const __half* hp = g_hh[t & 1] + l * B_ * H_;
        __half* hn = g_hh[(t + 1) & 1] + l * B_ * H_;
        int tl = (l & 1) ? (T_ - 1 - t) : t;

#pragma unroll
        for (int p = 0; p < NSTAGE - 1; p++)
            issue_A32(as0 + p * AS_STAGE_BYTES, hp, p, tid);

        // prefetch pre values into registers (hidden under the GEMM)
        float2 pr[2][2][4];
#pragma unroll
        for (int mi = 0; mi < 2; mi++)
#pragma unroll
            for (int hh = 0; hh < 2; hh++) {
                int  row = wr * 32 + mi * 16 + g + hh * 8;
                long pb  = ((long)row * T_ + tl) * G4;
#pragma unroll
                for (int gate = 0; gate < 4; gate++)
                    pr[mi][hh][gate] =
                        *(const float2*)(pre_l + pb + gate * H_ + u0);
            }

        float acc[2][4][4];
#pragma unroll
        for (int mi = 0; mi < 2; mi++)
#pragma unroll
            for (int ni = 0; ni < 4; ni++)
#pragma unroll
                for (int k = 0; k < 4; k++) acc[mi][ni][k] = 0.f;

        for (int st = 0; st < KT2; st++) {
            asm volatile("cp.async.wait_group %0;" :: "n"(NSTAGE - 2));
            __syncthreads();
            step_compute_stage(s, st & (NSTAGE - 1), st, acc, wr, g, t4, lane);
            int nk = st + NSTAGE - 1;
            if (nk < KT2)
                issue_A32(as0 + (nk & (NSTAGE - 1)) * AS_STAGE_BYTES, hp, nk, tid);
            else
                asm volatile("cp.async.commit_group;");
        }

        // epilogue: gates + state update (c in registers, h2 stores)
#pragma unroll
        for (int mi = 0; mi < 2; mi++) {
#pragma unroll
            for (int hh = 0; hh < 2; hh++) {
                int row = wr * 32 + mi * 16 + g + hh * 8;
                float hv[2];
#pragma unroll
                for (int p = 0; p < 2; p++) {
                    int k = hh * 2 + p;
                    float pi = p ? pr[mi][hh][0].y : pr[mi][hh][0].x;
                    float pj = p ? pr[mi][hh][1].y : pr[mi][hh][1].x;
                    float pf = p ? pr[mi][hh][2].y : pr[mi][hh][2].x;
                    float po = p ? pr[mi][hh][3].y : pr[mi][hh][3].x;
                    float zi = acc[mi][0][k] + pi;
                    float zj = acc[mi][1][k] + pj;
                    float zf = acc[mi][2][k] + pf;
                    float zo = acc[mi][3][k] + po;
                    float co = creg[mi][hh][p];
                    float fg = 1.f / (1.f + __expf(-(zf + 1.f)));
                    float ig = 1.f / (1.f + __expf(-zi));
                    float og = 1.f / (1.f + __expf(-zo));
                    float cn = co * fg + ig * tanhf(zj);
                    creg[mi][hh][p] = cn;
                    hv[p] = tanhf(cn) * og;
                }
                *(__half2*)(hn + row * H_ + u0) = __floats2half2_rn(hv[0], hv[1]);
            }
        }

        // per-LSTM software barrier (64 blocks) — proven construct
        __threadfence();
        __syncthreads();
        if (tid == 0) {
            unsigned long long a = atomicAdd(&g_arrive[l], 1ULL) + 1ULL;
            unsigned long long want = (a + 63ULL) >> 6;
            if ((a & 63ULL) == 0ULL) {
                atomicAdd(&g_release[l], 1ULL);
            } else {
                while (*(volatile unsigned long long*)&g_release[l] < want) { }
            }
            __threadfence();
        }
        __syncthreads();
    }

    // write final cell state for the gather/MLP stage
    float* c_l = g_c + l * B_ * H_;
#pragma unroll
    for (int mi = 0; mi < 2; mi++)
#pragma unroll
        for (int hh = 0; hh < 2; hh++) {
            int row = wr * 32 + mi * 16 + g + hh * 8;
            *(float2*)(c_l + row * H_ + u0) =
                make_float2(creg[mi][hh][0], creg[mi][hh][1]);
        }
}

// ===========================================================================
// Tail: gather + MLP (tf32 2-stage GEMM, unchanged)
// ===========================================================================
struct GemmSmem {
    float As[2][128][20];
    float Bs[2][16][136];
};

__device__ __forceinline__ void stage_tiles(
    const float* __restrict__ A, long lda,
    const float* __restrict__ Bm, long ldb,
    int K, long m0, long n0, GemmSmem* s, int buf, int k0)
{
    int tid = threadIdx.x;
    {
        int r = tid >> 2;
        int c = (tid & 3) * 4;
#pragma unroll
        for (int i = 0; i < 2; i++) {
            int row = r + i * 64;
            const float* p = A + (m0 + row) * lda + (k0 + c);
            float4 v;
            if (k0 + c + 3 < K) {
                v = *(const float4*)p;
            } else {
                v.x = (k0 + c + 0 < K) ? p[0] : 0.f;
                v.y = (k0 + c + 1 < K) ? p[1] : 0.f;
                v.z = (k0 + c + 2 < K) ? p[2] : 0.f;
                v.w = (k0 + c + 3 < K) ? p[3] : 0.f;
            }
            s->As[buf][row][c + 0] = f2tf32(v.x);
            s->As[buf][row][c + 1] = f2tf32(v.y);
            s->As[buf][row][c + 2] = f2tf32(v.z);
            s->As[buf][row][c + 3] = f2tf32(v.w);
        }
    }
    {
        int r  = tid >> 4;
        int cb = (tid & 15) * 8;
#pragma unroll
        for (int j = 0; j < 2; j++) {
            int c = cb + j * 4;
            float4 v;
            if (k0 + r < K) {
                v = *(const float4*)(Bm + (long)(k0 + r) * ldb + n0 + c);
            } else {
                v.x = v.y = v.z = v.w = 0.f;
            }
            s->Bs[buf][r][c + 0] = f2tf32(v.x);
            s->Bs[buf][r][c + 1] = f2tf32(v.y);
            s->Bs[buf][r][c + 2] = f2tf32(v.z);
            s->Bs[buf][r][c + 3] = f2tf32(v.w);
        }
    }
}

__device__ __forceinline__ void gemm_main(
    const float* __restrict__ A, long lda,
    const float* __restrict__ Bm, long ldb,
    int K, long m0, long n0, GemmSmem* s, float acc[4][4][4])
{
    int lane = threadIdx.x & 31, wid = threadIdx.x >> 5;
    int wr = wid >> 2, wc = wid & 3, g = lane >> 2, t4 = lane & 3;
#pragma unroll
    for (int mi = 0; mi < 4; mi++)
#pragma unroll
        for (int ni = 0; ni < 4; ni++)
#pragma unroll
            for (int k = 0; k < 4; k++) acc[mi][ni][k] = 0.f;

    int nkt = (K + 15) >> 4;
    stage_tiles(A, lda, Bm, ldb, K, m0, n0, s, 0, 0);
    __syncthreads();
    for (int kt = 0; kt < nkt; kt++) {
        pre_compute(&s->As[kt & 1][0][0], &s->Bs[kt & 1][0][0], acc, wr, wc, g, t4);
        if (kt + 1 < nkt)
            stage_tiles(A, lda, Bm, ldb, K, m0, n0, s, (kt + 1) & 1, (kt + 1) * 16);
        __syncthreads();
    }
}

__global__ void k_gather()
{
    int idx = blockIdx.x * 256 + threadIdx.x;
    if (idx < B_ * G4) {
        int b = idx >> 11, kk = idx & 2047;
        int l = kk >> 9, gg = kk & 511;
        g_rnn[idx] = g_c[(long)l * B_ * H_ + (long)b * H_ + gg];
    }
}

__global__ __launch_bounds__(256) void k_dense(
    int a_sel, int K, const float* __restrict__ W, int N,
    const float* __restrict__ bias, int o_sel)
{
    long n0 = (long)blockIdx.x * 128, m0 = (long)blockIdx.y * 128;
    const float* A = (a_sel == 0) ? g_rnn : g_act[a_sel - 1];
    float* out = g_act[o_sel];
    __shared__ GemmSmem s;
    float acc[4][4][4];
    gemm_main(A, (a_sel == 0) ? G4 : F_, W, N, K, m0, n0, &s, acc);

    int lane = threadIdx.x & 31, wid = threadIdx.x >> 5;
    int wr = wid >> 2, wc = wid & 3, g = lane >> 2, t4 = lane & 3;
#pragma unroll
    for (int mi = 0; mi < 4; mi++)
#pragma unroll
        for (int ni = 0; ni < 4; ni++) {
            long col = n0 + wc * 32 + ni * 8 + t4 * 2;
            float bx = bias[col], by = bias[col + 1];
#pragma unroll
            for (int h = 0; h < 2; h++) {
                long row = m0 + wr * 64 + mi * 16 + g + h * 8;
                float2 v;
                v.x = tanhf(acc[mi][ni][h * 2 + 0] + bx);
                v.y = tanhf(acc[mi][ni][h * 2 + 1] + by);
                *(float2*)(out + row * (long)N + col) = v;
            }
        }
}

__global__ void k_logits(const float* __restrict__ W4,
                         const float* __restrict__ b4, float* __restrict__ out)
{
    int b = blockIdx.x, tid = threadIdx.x;
    const float* A = g_act[2] + (long)b * F_;
    float s0 = 0.f, s1 = 0.f, s2 = 0.f;
    for (int k = tid; k < F_; k += 128) {
        float a = A[k];
        s0 += a * W4[k * 3 + 0];
        s1 += a * W4[k * 3 + 1];
        s2 += a * W4[k * 3 + 2];
    }
#pragma unroll
    for (int off = 16; off; off >>= 1) {
        s0 += __shfl_down_sync(0xffffffffu, s0, off);
        s1 += __shfl_down_sync(0xffffffffu, s1, off);
        s2 += __shfl_down_sync(0xffffffffu, s2, off);
    }
    __shared__ float red[3][4];
    if ((tid & 31) == 0) {
        red[0][tid >> 5] = s0; red[1][tid >> 5] = s1; red[2][tid >> 5] = s2;
    }
    __syncthreads();
    if (tid == 0) {
        out[b * 3 + 0] = red[0][0] + red[0][1] + red[0][2] + red[0][3] + b4[0];
        out[b * 3 + 1] = red[1][0] + red[1][1] + red[1][2] + red[1][3] + b4[1];
        out[b * 3 + 2] = red[2][0] + red[2][1] + red[2][2] + red[2][3] + b4[2];
    }
}

// ---------------------------------------------------------------------------
// kernel_launch
// ---------------------------------------------------------------------------
extern "C" void kernel_launch(void* const* d_in, const int* in_sizes, int n_in,
                              void* d_out, int out_size)
{
    (void)in_sizes; (void)n_in; (void)out_size;
    const float* prem   = (const float*)d_in[0];
    const float* hyp    = (const float*)d_in[1];
    const float* W_fw_p = (const float*)d_in[2];
    const float* b_fw_p = (const float*)d_in[3];
    const float* W_bw_p = (const float*)d_in[4];
    const float* b_bw_p = (const float*)d_in[5];
    const float* W_fw_h = (const float*)d_in[6];
    const float* b_fw_h = (const float*)d_in[7];
    const float* W_bw_h = (const float*)d_in[8];
    const float* b_bw_h = (const float*)d_in[9];
    const float* W1 = (const float*)d_in[10];
    const float* b1 = (const float*)d_in[11];
    const float* W2 = (const float*)d_in[12];
    const float* b2 = (const float*)d_in[13];
    const float* W3 = (const float*)d_in[14];
    const float* b3 = (const float*)d_in[15];
    const float* W4 = (const float*)d_in[16];
    const float* b4 = (const float*)d_in[17];
    float* out = (float*)d_out;

    cudaFuncSetAttribute(k_step_persist,
                         cudaFuncAttributeMaxDynamicSharedMemorySize,
                         (int)STEP_SMEM_BYTES);
    cudaFuncSetAttribute(k_precompute2,
                         cudaFuncAttributeMaxDynamicSharedMemorySize,
                         (int)PRE_SMEM_BYTES);

    // Launch order matters for ncu (capture lands on launch index 3 = step).
    int nz = NL * B_ * H_;
    k_zero<<<(nz + 255) / 256, 256>>>();                              // 0

    long nx = 2L * BT * KP_;
    k_prep_all<<<(int)((nx + 255) / 256), 256>>>(
        prem, hyp, W_fw_p, W_bw_p, W_fw_h, W_bw_h);                   // 1

    k_precompute2<<<dim3(16, 256, 4), 256, PRE_SMEM_BYTES>>>(
        b_fw_p, b_bw_p, b_fw_h, b_bw_h);                              // 2

    k_step_persist<<<256, STEP_THREADS, STEP_SMEM_BYTES>>>();         // 3

    k_gather<<<(B_ * G4 + 255) / 256, 256>>>();                       // 4

    k_dense<<<dim3(8, 2), 256>>>(0, G4, W1, F_, b1, 0);               // 5
    k_dense<<<dim3(8, 2), 256>>>(1, F_, W2, F_, b2, 1);               // 6
    k_dense<<<dim3(8, 2), 256>>>(2, F_, W3, F_, b3, 2);               // 7

    k_logits<<<B_, 128>>>(W4, b4, out);                               // 8
}

// round 15
// speedup vs baseline: 1.3148x; 1.3148x over previous
#include <cuda_runtime.h>
#include <cuda_fp16.h>
#include <math.h>

// Problem constants
#define B_  256
#define T_  128
#define E_  300
#define H_  512
#define G4  2048          // 4*H
#define F_  1024
#define NL  4
#define BT  32768         // B*T
#define KPH 320           // E padded to 64 for fp16 precompute
#define PKT 10            // precompute: 10 stages of K=32
#define KT2 8             // recurrent: 8 stages of K=64
#define NSTAGE 4

// ---------------------------------------------------------------------------
// Device scratch (static; no allocations anywhere)
// ---------------------------------------------------------------------------
__device__ float  g_pre[268435456];           // [4][B*T][G4] = 1.07 GB
__device__ __align__(256) __half g_xh  [2 * BT * KPH];     // fp16 padded inputs
__device__ __align__(256) __half g_wxT [NL * G4 * KPH];    // fp16 Wx transposed [N,K]
__device__ float  g_wh [NL * H_ * G4];        // RAW fp32 recurrent weights
__device__ __align__(256) __half g_hh[2][NL * B_ * H_];    // fp16 hidden ping-pong
__device__ float  g_c  [NL * B_ * H_];        // cell state (final only)
__device__ float  g_rnn[B_ * G4];             // concat of final c's
__device__ float  g_act[3][B_ * F_];          // MLP activations
__device__ unsigned long long g_arrive [NL];
__device__ unsigned long long g_release[NL];

__device__ __forceinline__ float f2tf32(float x) {
    unsigned u;
    asm("cvt.rna.tf32.f32 %0, %1;" : "=r"(u) : "f"(x));
    return __uint_as_float(u);
}

// ===========================================================================
// k_zero: zero initial states (per replay)
// ===========================================================================
__global__ void k_zero()
{
    int idx = blockIdx.x * 256 + threadIdx.x;
    if (idx < NL * B_ * H_) {
        g_hh[0][idx] = __float2half(0.f);
        g_hh[1][idx] = __float2half(0.f);
    }
}

// ===========================================================================
// k_prep_all: fp16 conversion/padding for precompute; raw copy of Wh.
//   job 1: g_xh  [2][BT][320]    fp16, zero-padded
//   job 2: g_wxT [l][2048][320]  fp16, TRANSPOSED input weights
//   job 3: g_wh  [l][512][2048]  fp32 raw recurrent rows
// ===========================================================================
__global__ void k_prep_all(
    const float* __restrict__ prem, const float* __restrict__ hyp,
    const float* __restrict__ W0, const float* __restrict__ W1,
    const float* __restrict__ W2, const float* __restrict__ W3)
{
    long idx = (long)blockIdx.x * 256 + threadIdx.x;

    if (idx < 2L * BT * KPH) {
        int which = (int)(idx / ((long)BT * KPH));
        long rem  = idx - (long)which * BT * KPH;
        int row = (int)(rem / KPH), col = (int)(rem - (long)row * KPH);
        const float* x = which ? hyp : prem;
        g_xh[idx] = (col < E_) ? __float2half_rn(x[(long)row * E_ + col])
                               : __float2half(0.f);
    }
    if (idx < (long)NL * G4 * KPH) {
        int l = (int)(idx / ((long)G4 * KPH));
        long rem = idx - (long)l * G4 * KPH;
        int c = (int)(rem / KPH), k = (int)(rem - (long)c * KPH);
        const float* W = (l == 0) ? W0 : (l == 1) ? W1 : (l == 2) ? W2 : W3;
        g_wxT[idx] = (k < E_) ? __float2half_rn(W[(long)k * G4 + c])
                              : __float2half(0.f);
    }
    if (idx < (long)NL * H_ * G4) {
        int l = (int)(idx / ((long)H_ * G4));
        long rem = idx - (long)l * H_ * G4;
        int r = (int)(rem / G4), c = (int)(rem - (long)r * G4);
        const float* W = (l == 0) ? W0 : (l == 1) ? W1 : (l == 2) ? W2 : W3;
        g_wh[idx] = W[(long)(E_ + r) * G4 + c];
    }
}

// ===========================================================================
// fp16 precompute GEMM: g_pre[l] = Xh @ WxT^T + b_l
// 128x128 tile, 256 threads (8 warps: wr=wid>>1 m-strip32, wc=wid&1 n-strip64)
// A [128 rows x 32 halves/stage], B [128 n-rows x 32 k-halves/stage] (both
// stride-40), 10 stages of K=32, 4-stage cp.async. 80 KB smem -> 2 blocks/SM.
// ===========================================================================
struct PreSmem {
    __half As[NSTAGE][128][40];    // 10 KB/stage
    __half Bs[NSTAGE][128][40];    // 10 KB/stage
};
#define PRE_SMEM_BYTES sizeof(PreSmem)
#define PRE_STAGE_BYTES (128 * 40 * 2)

__device__ __forceinline__ void pre16_issue(
    unsigned sA, unsigned sB, const __half* __restrict__ A,
    const __half* __restrict__ Bm, int s, int tid)
{
#pragma unroll
    for (int i = 0; i < 2; i++) {
        int c = tid + i * 256;               // 0..511 chunks of 16B
        int row = c >> 2, ch = c & 3;
        unsigned dst = sA + (unsigned)(row * 40 + ch * 8) * 2u;
        const __half* src = A + (long)row * KPH + s * 32 + ch * 8;
        asm volatile("cp.async.cg.shared.global [%0], [%1], 16;"
                     :: "r"(dst), "l"(src));
    }
#pragma unroll
    for (int i = 0; i < 2; i++) {
        int c = tid + i * 256;
        int row = c >> 2, ch = c & 3;
        unsigned dst = sB + (unsigned)(row * 40 + ch * 8) * 2u;
        const __half* src = Bm + (long)row * KPH + s * 32 + ch * 8;
        asm volatile("cp.async.cg.shared.global [%0], [%1], 16;"
                     :: "r"(dst), "l"(src));
    }
    asm volatile("cp.async.commit_group;");
}

__device__ __forceinline__ void pre16_compute(
    const PreSmem* s, int stg, float acc[2][8][4],
    int wr, int wc, int g, int t4)
{
    const __half* As = &s->As[stg][0][0];
    const __half* Bs = &s->Bs[stg][0][0];
#pragma unroll
    for (int ks = 0; ks < 2; ks++) {
        int kh = ks * 16;
        unsigned af[2][4], bf[8][2];
#pragma unroll
        for (int mi = 0; mi < 2; mi++) {
            int r0 = (wr * 32 + mi * 16 + g) * 40;
            int r1 = r0 + 8 * 40;
            af[mi][0] = *(const unsigned*)(As + r0 + kh + 2 * t4);
            af[mi][1] = *(const unsigned*)(As + r1 + kh + 2 * t4);
            af[mi][2] = *(const unsigned*)(As + r0 + kh + 8 + 2 * t4);
            af[mi][3] = *(const unsigned*)(As + r1 + kh + 8 + 2 * t4);
        }
#pragma unroll
        for (int ni = 0; ni < 8; ni++) {
            int rb = (wc * 64 + ni * 8 + g) * 40;
            bf[ni][0] = *(const unsigned*)(Bs + rb + kh + 2 * t4);
            bf[ni][1] = *(const unsigned*)(Bs + rb + kh + 8 + 2 * t4);
        }
#pragma unroll
        for (int mi = 0; mi < 2; mi++)
#pragma unroll
            for (int ni = 0; ni < 8; ni++)
                asm volatile(
                    "mma.sync.aligned.m16n8k16.row.col.f32.f16.f16.f32 "
                    "{%0,%1,%2,%3},{%4,%5,%6,%7},{%8,%9},{%0,%1,%2,%3};"
                    : "+f"(acc[mi][ni][0]), "+f"(acc[mi][ni][1]),
                      "+f"(acc[mi][ni][2]), "+f"(acc[mi][ni][3])
                    : "r"(af[mi][0]), "r"(af[mi][1]), "r"(af[mi][2]), "r"(af[mi][3]),
                      "r"(bf[ni][0]), "r"(bf[ni][1]));
    }
}

__global__ __launch_bounds__(256, 2) void k_precompute16(
    const float* __restrict__ b0, const float* __restrict__ b1,
    const float* __restrict__ b2, const float* __restrict__ b3)
{
    extern __shared__ char raw[];
    PreSmem* s = (PreSmem*)raw;
    unsigned sAb = (unsigned)__cvta_generic_to_shared(&s->As[0][0][0]);
    unsigned sBb = (unsigned)__cvta_generic_to_shared(&s->Bs[0][0][0]);

    int tid = threadIdx.x, lane = tid & 31, wid = tid >> 5;
    int wr = wid >> 1, wc = wid & 1, g = lane >> 2, t4 = lane & 3;
    int l = blockIdx.z;
    long n0 = (long)blockIdx.x * 128, m0 = (long)blockIdx.y * 128;
    const __half* A  = g_xh  + (long)(l >> 1) * BT * KPH + m0 * KPH;
    const __half* Bm = g_wxT + (long)l * G4 * KPH + n0 * KPH;
    const float*  bb = (l == 0) ? b0 : (l == 1) ? b1 : (l == 2) ? b2 : b3;

    float acc[2][8][4];
#pragma unroll
    for (int mi = 0; mi < 2; mi++)
#pragma unroll
        for (int ni = 0; ni < 8; ni++)
#pragma unroll
            for (int k = 0; k < 4; k++) acc[mi][ni][k] = 0.f;

#pragma unroll
    for (int p = 0; p < NSTAGE - 1; p++)
        pre16_issue(sAb + p * PRE_STAGE_BYTES, sBb + p * PRE_STAGE_BYTES,
                    A, Bm, p, tid);

    for (int st = 0; st < PKT; st++) {
        asm volatile("cp.async.wait_group %0;" :: "n"(NSTAGE - 2));
        __syncthreads();
        pre16_compute(s, st & (NSTAGE - 1), acc, wr, wc, g, t4);
        int nk = st + NSTAGE - 1;
        if (nk < PKT)
            pre16_issue(sAb + (nk & (NSTAGE - 1)) * PRE_STAGE_BYTES,
                        sBb + (nk & (NSTAGE - 1)) * PRE_STAGE_BYTES,
                        A, Bm, nk, tid);
        else
            asm volatile("cp.async.commit_group;");
    }

    float* out = g_pre + (long)l * BT * G4;
#pragma unroll
    for (int mi = 0; mi < 2; mi++)
#pragma unroll
        for (int ni = 0; ni < 8; ni++) {
            long col = n0 + wc * 64 + ni * 8 + t4 * 2;
            float bx = bb[col], by = bb[col + 1];
#pragma unroll
            for (int h = 0; h < 2; h++) {
                long row = m0 + wr * 32 + mi * 16 + g + h * 8;
                float2 v;
                v.x = acc[mi][ni][h * 2 + 0] + bx;
                v.y = acc[mi][ni][h * 2 + 1] + by;
                *(float2*)(out + row * G4 + col) = v;
            }
        }
}

// ===========================================================================
// Persistent recurrent kernel (128 blocks, 1/SM, 512 threads) — fp16 GEMM.
// Round-12 proven config. block = (l = bid>>5, nb = bid&31): 16 units x 4
// gates, M=256, K=512; 16 warps (wr=wid>>1 m-strip32, wc=wid&1 n-strip32).
// ===========================================================================
#define STEP_THREADS 512

struct StepSmem {
    uint2  Wfrag[256][32];           // 64 KB
    __half As[NSTAGE][256][72];      // 144 KB
};
#define STEP_SMEM_BYTES sizeof(StepSmem)
#define AS_STAGE_BYTES (256 * 72 * 2)

__device__ __forceinline__ void issue_A64(unsigned as_base_b, const __half* hp,
                                          int s, int tid)
{
#pragma unroll
    for (int i = 0; i < 4; i++) {
        int c = tid + i * STEP_THREADS;      // 0..2047 chunks of 16B
        int row = c >> 3, ch = c & 7;
        unsigned dst = as_base_b + (unsigned)(row * 72 + ch * 8) * 2u;
        const __half* src = hp + row * 512 + s * 64 + ch * 8;
        asm volatile("cp.async.cg.shared.global [%0], [%1], 16;"
                     :: "r"(dst), "l"(src));
    }
    asm volatile("cp.async.commit_group;");
}

__device__ __forceinline__ void step_compute_stage(
    const StepSmem* s, int stg, int st, float acc[2][4][4],
    int wr, int wc, int g, int t4, int lane)
{
    const __half* As = &s->As[stg][0][0];
#pragma unroll
    for (int ks = 0; ks < 4; ks++) {
        int kh = ks * 16;
        unsigned af[2][4];
        uint2    bf[4];
#pragma unroll
        for (int mi = 0; mi < 2; mi++) {
            int r0 = (wr * 32 + mi * 16 + g) * 72;
            int r1 = r0 + 8 * 72;
            af[mi][0] = *(const unsigned*)(As + r0 + kh + 2 * t4);
            af[mi][1] = *(const unsigned*)(As + r1 + kh + 2 * t4);
            af[mi][2] = *(const unsigned*)(As + r0 + kh + 8 + 2 * t4);
            af[mi][3] = *(const unsigned*)(As + r1 + kh + 8 + 2 * t4);
        }
        int kt = st * 4 + ks;
#pragma unroll
        for (int ni = 0; ni < 4; ni++)
            bf[ni] = s->Wfrag[kt * 8 + wc * 4 + ni][lane];
#pragma unroll
        for (int mi = 0; mi < 2; mi++)
#pragma unroll
            for (int ni = 0; ni < 4; ni++)
                asm volatile(
                    "mma.sync.aligned.m16n8k16.row.col.f32.f16.f16.f32 "
                    "{%0,%1,%2,%3},{%4,%5,%6,%7},{%8,%9},{%0,%1,%2,%3};"
                    : "+f"(acc[mi][ni][0]), "+f"(acc[mi][ni][1]),
                      "+f"(acc[mi][ni][2]), "+f"(acc[mi][ni][3])
                    : "r"(af[mi][0]), "r"(af[mi][1]), "r"(af[mi][2]), "r"(af[mi][3]),
                      "r"(bf[ni].x), "r"(bf[ni].y));
    }
}

__global__ __launch_bounds__(STEP_THREADS, 1) void k_step_persist()
{
    extern __shared__ char raw[];
    StepSmem* s = (StepSmem*)raw;
    int tid = threadIdx.x, lane = tid & 31, wid = tid >> 5;
    int wr = wid >> 1, wc = wid & 1, g = lane >> 2, t4 = lane & 3;
    int bid = blockIdx.x, l = bid >> 5, nb = bid & 31;
    const float* Wh = g_wh + (long)l * H_ * G4;

    // one-time: build fp16 B-fragments in smem (m16n8k16 layout).
    for (int f = wid; f < 256; f += 16) {
        int kt = f >> 3, rest = f & 7, wcf = rest >> 2, ni = rest & 3;
        int col = ni * H_ + nb * 16 + wcf * 8 + g;
        int k0  = kt * 16 + 2 * t4;
        float w0 = Wh[(long)(k0    ) * G4 + col];
        float w1 = Wh[(long)(k0 + 1) * G4 + col];
        float w2 = Wh[(long)(k0 + 8) * G4 + col];
        float w3 = Wh[(long)(k0 + 9) * G4 + col];
        __half2 p0 = __floats2half2_rn(w0, w1);
        __half2 p1 = __floats2half2_rn(w2, w3);
        uint2 v;
        v.x = *(unsigned*)&p0;
        v.y = *(unsigned*)&p1;
        s->Wfrag[f][lane] = v;
    }
    __syncthreads();

    const float* pre_l = g_pre + (long)l * BT * G4;
    unsigned as0 = (unsigned)__cvta_generic_to_shared(&s->As[0][0][0]);
    int u0 = nb * 16 + wc * 8 + t4 * 2;

    float creg[2][2][2];
#pragma unroll
    for (int mi = 0; mi < 2; mi++)
#pragma unroll
        for (int hh = 0; hh < 2; hh++) {
            creg[mi][hh][0] = 0.f;
            creg[mi][hh][1] = 0.f;
        }

    for (int t = 0; t < T_; t++) {
        const __half* hp = g_hh[t & 1] + l * B_ * H_;
        __half* hn = g_hh[(t + 1) & 1] + l * B_ * H_;
        int tl = (l & 1) ? (T_ - 1 - t) : t;

#pragma unroll
        for (int p = 0; p < NSTAGE - 1; p++)
            issue_A64(as0 + p * AS_STAGE_BYTES, hp, p, tid);

        float2 pr[2][2][4];
#pragma unroll
        for (int mi = 0; mi < 2; mi++)
#pragma unroll
            for (int hh = 0; hh < 2; hh++) {
                int  row = wr * 32 + mi * 16 + g + hh * 8;
                long pb  = ((long)row * T_ + tl) * G4;
#pragma unroll
                for (int gate = 0; gate < 4; gate++)
                    pr[mi][hh][gate] =
                        *(const float2*)(pre_l + pb + gate * H_ + u0);
            }

        float acc[2][4][4];
#pragma unroll
        for (int mi = 0; mi < 2; mi++)
#pragma unroll
            for (int ni = 0; ni < 4; ni++)
#pragma unroll
                for (int k = 0; k < 4; k++) acc[mi][ni][k] = 0.f;

        for (int st = 0; st < KT2; st++) {
            asm volatile("cp.async.wait_group %0;" :: "n"(NSTAGE - 2));
            __syncthreads();
            step_compute_stage(s, st & (NSTAGE - 1), st, acc, wr, wc, g, t4, lane);
            int nk = st + NSTAGE - 1;
            if (nk < KT2)
                issue_A64(as0 + (nk & (NSTAGE - 1)) * AS_STAGE_BYTES, hp, nk, tid);
            else
                asm volatile("cp.async.commit_group;");
        }

#pragma unroll
        for (int mi = 0; mi < 2; mi++) {
#pragma unroll
            for (int hh = 0; hh < 2; hh++) {
                int row = wr * 32 + mi * 16 + g + hh * 8;
                float hv[2];
#pragma unroll
                for (int p = 0; p < 2; p++) {
                    int k = hh * 2 + p;
                    float pi = p ? pr[mi][hh][0].y : pr[mi][hh][0].x;
                    float pj = p ? pr[mi][hh][1].y : pr[mi][hh][1].x;
                    float pf = p ? pr[mi][hh][2].y : pr[mi][hh][2].x;
                    float po = p ? pr[mi][hh][3].y : pr[mi][hh][3].x;
                    float zi = acc[mi][0][k] + pi;
                    float zj = acc[mi][1][k] + pj;
                    float zf = acc[mi][2][k] + pf;
                    float zo = acc[mi][3][k] + po;
                    float co = creg[mi][hh][p];
                    float fg = 1.f / (1.f + __expf(-(zf + 1.f)));
                    float ig = 1.f / (1.f + __expf(-zi));
                    float og = 1.f / (1.f + __expf(-zo));
                    float cn = co * fg + ig * tanhf(zj);
                    creg[mi][hh][p] = cn;
                    hv[p] = tanhf(cn) * og;
                }
                *(__half2*)(hn + row * H_ + u0) = __floats2half2_rn(hv[0], hv[1]);
            }
        }

        // per-LSTM software barrier (32 blocks) — proven construct
        __threadfence();
        __syncthreads();
        if (tid == 0) {
            unsigned long long a = atomicAdd(&g_arrive[l], 1ULL) + 1ULL;
            unsigned long long want = (a + 31ULL) >> 5;
            if ((a & 31ULL) == 0ULL) {
                atomicAdd(&g_release[l], 1ULL);
            } else {
                while (*(volatile unsigned long long*)&g_release[l] < want) { }
            }
            __threadfence();
        }
        __syncthreads();
    }

    float* c_l = g_c + l * B_ * H_;
#pragma unroll
    for (int mi = 0; mi < 2; mi++)
#pragma unroll
        for (int hh = 0; hh < 2; hh++) {
            int row = wr * 32 + mi * 16 + g + hh * 8;
            *(float2*)(c_l + row * H_ + u0) =
                make_float2(creg[mi][hh][0], creg[mi][hh][1]);
        }
}

// ===========================================================================
// Tail: gather + MLP (tf32 2-stage GEMM, unchanged)
// ===========================================================================
struct GemmSmem {
    float As[2][128][20];
    float Bs[2][16][136];
};

__device__ __forceinline__ void stage_tiles(
    const float* __restrict__ A, long lda,
    const float* __restrict__ Bm, long ldb,
    int K, long m0, long n0, GemmSmem* s, int buf, int k0)
{
    int tid = threadIdx.x;
    {
        int r = tid >> 2;
        int c = (tid & 3) * 4;
#pragma unroll
        for (int i = 0; i < 2; i++) {
            int row = r + i * 64;
            const float* p = A + (m0 + row) * lda + (k0 + c);
            float4 v;
            if (k0 + c + 3 < K) {
                v = *(const float4*)p;
            } else {
                v.x = (k0 + c + 0 < K) ? p[0] : 0.f;
                v.y = (k0 + c + 1 < K) ? p[1] : 0.f;
                v.z = (k0 + c + 2 < K) ? p[2] : 0.f;
                v.w = (k0 + c + 3 < K) ? p[3] : 0.f;
            }
            s->As[buf][row][c + 0] = f2tf32(v.x);
            s->As[buf][row][c + 1] = f2tf32(v.y);
            s->As[buf][row][c + 2] = f2tf32(v.z);
            s->As[buf][row][c + 3] = f2tf32(v.w);
        }
    }
    {
        int r  = tid >> 4;
        int cb = (tid & 15) * 8;
#pragma unroll
        for (int j = 0; j < 2; j++) {
            int c = cb + j * 4;
            float4 v;
            if (k0 + r < K) {
                v = *(const float4*)(Bm + (long)(k0 + r) * ldb + n0 + c);
            } else {
                v.x = v.y = v.z = v.w = 0.f;
            }
            s->Bs[buf][r][c + 0] = f2tf32(v.x);
            s->Bs[buf][r][c + 1] = f2tf32(v.y);
            s->Bs[buf][r][c + 2] = f2tf32(v.z);
            s->Bs[buf][r][c + 3] = f2tf32(v.w);
        }
    }
}

__device__ __forceinline__ void tf32_compute(
    const float* As, const float* Bs, float acc[4][4][4],
    int wr, int wc, int g, int t4)
{
#pragma unroll
    for (int ks = 0; ks < 2; ks++) {
        int k0 = ks * 8;
        unsigned af[4][4], bf[4][2];
#pragma unroll
        for (int mi = 0; mi < 4; mi++) {
            int rb = wr * 64 + mi * 16;
            af[mi][0] = __float_as_uint(As[(rb + g    ) * 20 + k0 + t4    ]);
            af[mi][1] = __float_as_uint(As[(rb + g + 8) * 20 + k0 + t4    ]);
            af[mi][2] = __float_as_uint(As[(rb + g    ) * 20 + k0 + t4 + 4]);
            af[mi][3] = __float_as_uint(As[(rb + g + 8) * 20 + k0 + t4 + 4]);
        }
#pragma unroll
        for (int ni = 0; ni < 4; ni++) {
            int cb = wc * 32 + ni * 8;
            bf[ni][0] = __float_as_uint(Bs[(k0 + t4    ) * 136 + cb + g]);
            bf[ni][1] = __float_as_uint(Bs[(k0 + t4 + 4) * 136 + cb + g]);
        }
#pragma unroll
        for (int mi = 0; mi < 4; mi++)
#pragma unroll
            for (int ni = 0; ni < 4; ni++)
                asm volatile(
                    "mma.sync.aligned.m16n8k8.row.col.f32.tf32.tf32.f32 "
                    "{%0,%1,%2,%3},{%4,%5,%6,%7},{%8,%9},{%0,%1,%2,%3};"
                    : "+f"(acc[mi][ni][0]), "+f"(acc[mi][ni][1]),
                      "+f"(acc[mi][ni][2]), "+f"(acc[mi][ni][3])
                    : "r"(af[mi][0]), "r"(af[mi][1]), "r"(af[mi][2]), "r"(af[mi][3]),
                      "r"(bf[ni][0]), "r"(bf[ni][1]));
    }
}

__device__ __forceinline__ void gemm_main(
    const float* __restrict__ A, long lda,
    const float* __restrict__ Bm, long ldb,
    int K, long m0, long n0, GemmSmem* s, float acc[4][4][4])
{
    int lane = threadIdx.x & 31, wid = threadIdx.x >> 5;
    int wr = wid >> 2, wc = wid & 3, g = lane >> 2, t4 = lane & 3;
#pragma unroll
    for (int mi = 0; mi < 4; mi++)
#pragma unroll
        for (int ni = 0; ni < 4; ni++)
#pragma unroll
            for (int k = 0; k < 4; k++) acc[mi][ni][k] = 0.f;

    int nkt = (K + 15) >> 4;
    stage_tiles(A, lda, Bm, ldb, K, m0, n0, s, 0, 0);
    __syncthreads();
    for (int kt = 0; kt < nkt; kt++) {
        tf32_compute(&s->As[kt & 1][0][0], &s->Bs[kt & 1][0][0], acc, wr, wc, g, t4);
        if (kt + 1 < nkt)
            stage_tiles(A, lda, Bm, ldb, K, m0, n0, s, (kt + 1) & 1, (kt + 1) * 16);
        __syncthreads();
    }
}

__global__ void k_gather()
{
    int idx = blockIdx.x * 256 + threadIdx.x;
    if (idx < B_ * G4) {
        int b = idx >> 11, kk = idx & 2047;
        int l = kk >> 9, gg = kk & 511;
        g_rnn[idx] = g_c[(long)l * B_ * H_ + (long)b * H_ + gg];
    }
}

__global__ __launch_bounds__(256) void k_dense(
    int a_sel, int K, const float* __restrict__ W, int N,
    const float* __restrict__ bias, int o_sel)
{
    long n0 = (long)blockIdx.x * 128, m0 = (long)blockIdx.y * 128;
    const float* A = (a_sel == 0) ? g_rnn : g_act[a_sel - 1];
    float* out = g_act[o_sel];
    __shared__ GemmSmem s;
    float acc[4][4][4];
    gemm_main(A, (a_sel == 0) ? G4 : F_, W, N, K, m0, n0, &s, acc);

    int lane = threadIdx.x & 31, wid = threadIdx.x >> 5;
    int wr = wid >> 2, wc = wid & 3, g = lane >> 2, t4 = lane & 3;
#pragma unroll
    for (int mi = 0; mi < 4; mi++)
#pragma unroll
        for (int ni = 0; ni < 4; ni++) {
            long col = n0 + wc * 32 + ni * 8 + t4 * 2;
            float bx = bias[col], by = bias[col + 1];
#pragma unroll
            for (int h = 0; h < 2; h++) {
                long row = m0 + wr * 64 + mi * 16 + g + h * 8;
                float2 v;
                v.x = tanhf(acc[mi][ni][h * 2 + 0] + bx);
                v.y = tanhf(acc[mi][ni][h * 2 + 1] + by);
                *(float2*)(out + row * (long)N + col) = v;
            }
        }
}

__global__ void k_logits(const float* __restrict__ W4,
                         const float* __restrict__ b4, float* __restrict__ out)
{
    int b = blockIdx.x, tid = threadIdx.x;
    const float* A = g_act[2] + (long)b * F_;
    float s0 = 0.f, s1 = 0.f, s2 = 0.f;
    for (int k = tid; k < F_; k += 128) {
        float a = A[k];
        s0 += a * W4[k * 3 + 0];
        s1 += a * W4[k * 3 + 1];
        s2 += a * W4[k * 3 + 2];
    }
#pragma unroll
    for (int off = 16; off; off >>= 1) {
        s0 += __shfl_down_sync(0xffffffffu, s0, off);
        s1 += __shfl_down_sync(0xffffffffu, s1, off);
        s2 += __shfl_down_sync(0xffffffffu, s2, off);
    }
    __shared__ float red[3][4];
    if ((tid & 31) == 0) {
        red[0][tid >> 5] = s0; red[1][tid >> 5] = s1; red[2][tid >> 5] = s2;
    }
    __syncthreads();
    if (tid == 0) {
        out[b * 3 + 0] = red[0][0] + red[0][1] + red[0][2] + red[0][3] + b4[0];
        out[b * 3 + 1] = red[1][0] + red[1][1] + red[1][2] + red[1][3] + b4[1];
        out[b * 3 + 2] = red[2][0] + red[2][1] + red[2][2] + red[2][3] + b4[2];
    }
}

// ---------------------------------------------------------------------------
// kernel_launch
// ---------------------------------------------------------------------------
extern "C" void kernel_launch(void* const* d_in, const int* in_sizes, int n_in,
                              void* d_out, int out_size)
{
    (void)in_sizes; (void)n_in; (void)out_size;
    const float* prem   = (const float*)d_in[0];
    const float* hyp    = (const float*)d_in[1];
    const float* W_fw_p = (const float*)d_in[2];
    const float* b_fw_p = (const float*)d_in[3];
    const float* W_bw_p = (const float*)d_in[4];
    const float* b_bw_p = (const float*)d_in[5];
    const float* W_fw_h = (const float*)d_in[6];
    const float* b_fw_h = (const float*)d_in[7];
    const float* W_bw_h = (const float*)d_in[8];
    const float* b_bw_h = (const float*)d_in[9];
    const float* W1 = (const float*)d_in[10];
    const float* b1 = (const float*)d_in[11];
    const float* W2 = (const float*)d_in[12];
    const float* b2 = (const float*)d_in[13];
    const float* W3 = (const float*)d_in[14];
    const float* b3 = (const float*)d_in[15];
    const float* W4 = (const float*)d_in[16];
    const float* b4 = (const float*)d_in[17];
    float* out = (float*)d_out;

    cudaFuncSetAttribute(k_step_persist,
                         cudaFuncAttributeMaxDynamicSharedMemorySize,
                         (int)STEP_SMEM_BYTES);
    cudaFuncSetAttribute(k_precompute16,
                         cudaFuncAttributeMaxDynamicSharedMemorySize,
                         (int)PRE_SMEM_BYTES);

    // Launch order matters for ncu (capture lands on launch index 3 = step).
    int nz = NL * B_ * H_;
    k_zero<<<(nz + 255) / 256, 256>>>();                              // 0

    long nx = 2L * BT * KPH;
    k_prep_all<<<(int)((nx + 255) / 256), 256>>>(
        prem, hyp, W_fw_p, W_bw_p, W_fw_h, W_bw_h);                   // 1

    k_precompute16<<<dim3(16, 256, 4), 256, PRE_SMEM_BYTES>>>(
        b_fw_p, b_bw_p, b_fw_h, b_bw_h);                              // 2

    k_step_persist<<<128, STEP_THREADS, STEP_SMEM_BYTES>>>();         // 3

    k_gather<<<(B_ * G4 + 255) / 256, 256>>>();                       // 4

    k_dense<<<dim3(8, 2), 256>>>(0, G4, W1, F_, b1, 0);               // 5
    k_dense<<<dim3(8, 2), 256>>>(1, F_, W2, F_, b2, 1);               // 6
    k_dense<<<dim3(8, 2), 256>>>(2, F_, W3, F_, b3, 2);               // 7

    k_logits<<<B_, 128>>>(W4, b4, out);                               // 8
}

// round 16
// speedup vs baseline: 1.4324x; 1.0894x over previous
#include <cuda_runtime.h>
#include <cuda_fp16.h>
#include <math.h>

// Problem constants
#define B_  256
#define T_  128
#define E_  300
#define H_  512
#define G4  2048          // 4*H
#define F_  1024
#define NL  4
#define BT  32768         // B*T
#define KPH 320           // E padded to 64 for fp16 precompute
#define PKT 10            // precompute: 10 stages of K=32
#define KT2 8             // recurrent: 8 stages of K=64
#define NSTAGE 4

// ---------------------------------------------------------------------------
// Device scratch (static; no allocations anywhere)
// ---------------------------------------------------------------------------
__device__ float  g_pre[268435456];           // [4][B*T][G4] = 1.07 GB
__device__ __align__(256) __half g_xh  [2 * BT * KPH];     // fp16 padded inputs
__device__ __align__(256) __half g_wxT [NL * G4 * KPH];    // fp16 Wx transposed [N,K]
__device__ float  g_wh [NL * H_ * G4];        // RAW fp32 recurrent weights
__device__ __align__(256) __half g_hh[2][NL * B_ * H_];    // fp16 hidden ping-pong
__device__ float  g_c  [NL * B_ * H_];        // cell state (final only)
__device__ float  g_rnn[B_ * G4];             // concat of final c's
__device__ float  g_act[3][B_ * F_];          // MLP activations
__device__ unsigned long long g_arrive [NL];
__device__ unsigned long long g_release[NL];

__device__ __forceinline__ float f2tf32(float x) {
    unsigned u;
    asm("cvt.rna.tf32.f32 %0, %1;" : "=r"(u) : "f"(x));
    return __uint_as_float(u);
}

// ===========================================================================
// k_zero: zero initial states (per replay)
// ===========================================================================
__global__ void k_zero()
{
    int idx = blockIdx.x * 256 + threadIdx.x;
    if (idx < NL * B_ * H_) {
        g_hh[0][idx] = __float2half(0.f);
        g_hh[1][idx] = __float2half(0.f);
    }
}

// ===========================================================================
// k_prep_all: fp16 conversion/padding for precompute; raw copy of Wh.
// ===========================================================================
__global__ void k_prep_all(
    const float* __restrict__ prem, const float* __restrict__ hyp,
    const float* __restrict__ W0, const float* __restrict__ W1,
    const float* __restrict__ W2, const float* __restrict__ W3)
{
    long idx = (long)blockIdx.x * 256 + threadIdx.x;

    if (idx < 2L * BT * KPH) {
        int which = (int)(idx / ((long)BT * KPH));
        long rem  = idx - (long)which * BT * KPH;
        int row = (int)(rem / KPH), col = (int)(rem - (long)row * KPH);
        const float* x = which ? hyp : prem;
        g_xh[idx] = (col < E_) ? __float2half_rn(x[(long)row * E_ + col])
                               : __float2half(0.f);
    }
    if (idx < (long)NL * G4 * KPH) {
        int l = (int)(idx / ((long)G4 * KPH));
        long rem = idx - (long)l * G4 * KPH;
        int c = (int)(rem / KPH), k = (int)(rem - (long)c * KPH);
        const float* W = (l == 0) ? W0 : (l == 1) ? W1 : (l == 2) ? W2 : W3;
        g_wxT[idx] = (k < E_) ? __float2half_rn(W[(long)k * G4 + c])
                              : __float2half(0.f);
    }
    if (idx < (long)NL * H_ * G4) {
        int l = (int)(idx / ((long)H_ * G4));
        long rem = idx - (long)l * H_ * G4;
        int r = (int)(rem / G4), c = (int)(rem - (long)r * G4);
        const float* W = (l == 0) ? W0 : (l == 1) ? W1 : (l == 2) ? W2 : W3;
        g_wh[idx] = W[(long)(E_ + r) * G4 + c];
    }
}

// ===========================================================================
// fp16 precompute GEMM: g_pre[l] = Xh @ WxT^T + b_l  (proven round-15)
// ===========================================================================
struct PreSmem {
    __half As[NSTAGE][128][40];
    __half Bs[NSTAGE][128][40];
};
#define PRE_SMEM_BYTES sizeof(PreSmem)
#define PRE_STAGE_BYTES (128 * 40 * 2)

__device__ __forceinline__ void pre16_issue(
    unsigned sA, unsigned sB, const __half* __restrict__ A,
    const __half* __restrict__ Bm, int s, int tid)
{
#pragma unroll
    for (int i = 0; i < 2; i++) {
        int c = tid + i * 256;
        int row = c >> 2, ch = c & 3;
        unsigned dst = sA + (unsigned)(row * 40 + ch * 8) * 2u;
        const __half* src = A + (long)row * KPH + s * 32 + ch * 8;
        asm volatile("cp.async.cg.shared.global [%0], [%1], 16;"
                     :: "r"(dst), "l"(src));
    }
#pragma unroll
    for (int i = 0; i < 2; i++) {
        int c = tid + i * 256;
        int row = c >> 2, ch = c & 3;
        unsigned dst = sB + (unsigned)(row * 40 + ch * 8) * 2u;
        const __half* src = Bm + (long)row * KPH + s * 32 + ch * 8;
        asm volatile("cp.async.cg.shared.global [%0], [%1], 16;"
                     :: "r"(dst), "l"(src));
    }
    asm volatile("cp.async.commit_group;");
}

__device__ __forceinline__ void pre16_compute(
    const PreSmem* s, int stg, float acc[2][8][4],
    int wr, int wc, int g, int t4)
{
    const __half* As = &s->As[stg][0][0];
    const __half* Bs = &s->Bs[stg][0][0];
#pragma unroll
    for (int ks = 0; ks < 2; ks++) {
        int kh = ks * 16;
        unsigned af[2][4], bf[8][2];
#pragma unroll
        for (int mi = 0; mi < 2; mi++) {
            int r0 = (wr * 32 + mi * 16 + g) * 40;
            int r1 = r0 + 8 * 40;
            af[mi][0] = *(const unsigned*)(As + r0 + kh + 2 * t4);
            af[mi][1] = *(const unsigned*)(As + r1 + kh + 2 * t4);
            af[mi][2] = *(const unsigned*)(As + r0 + kh + 8 + 2 * t4);
            af[mi][3] = *(const unsigned*)(As + r1 + kh + 8 + 2 * t4);
        }
#pragma unroll
        for (int ni = 0; ni < 8; ni++) {
            int rb = (wc * 64 + ni * 8 + g) * 40;
            bf[ni][0] = *(const unsigned*)(Bs + rb + kh + 2 * t4);
            bf[ni][1] = *(const unsigned*)(Bs + rb + kh + 8 + 2 * t4);
        }
#pragma unroll
        for (int mi = 0; mi < 2; mi++)
#pragma unroll
            for (int ni = 0; ni < 8; ni++)
                asm volatile(
                    "mma.sync.aligned.m16n8k16.row.col.f32.f16.f16.f32 "
                    "{%0,%1,%2,%3},{%4,%5,%6,%7},{%8,%9},{%0,%1,%2,%3};"
                    : "+f"(acc[mi][ni][0]), "+f"(acc[mi][ni][1]),
                      "+f"(acc[mi][ni][2]), "+f"(acc[mi][ni][3])
                    : "r"(af[mi][0]), "r"(af[mi][1]), "r"(af[mi][2]), "r"(af[mi][3]),
                      "r"(bf[ni][0]), "r"(bf[ni][1]));
    }
}

__global__ __launch_bounds__(256, 2) void k_precompute16(
    const float* __restrict__ b0, const float* __restrict__ b1,
    const float* __restrict__ b2, const float* __restrict__ b3)
{
    extern __shared__ char raw[];
    PreSmem* s = (PreSmem*)raw;
    unsigned sAb = (unsigned)__cvta_generic_to_shared(&s->As[0][0][0]);
    unsigned sBb = (unsigned)__cvta_generic_to_shared(&s->Bs[0][0][0]);

    int tid = threadIdx.x, lane = tid & 31, wid = tid >> 5;
    int wr = wid >> 1, wc = wid & 1, g = lane >> 2, t4 = lane & 3;
    int l = blockIdx.z;
    long n0 = (long)blockIdx.x * 128, m0 = (long)blockIdx.y * 128;
    const __half* A  = g_xh  + (long)(l >> 1) * BT * KPH + m0 * KPH;
    const __half* Bm = g_wxT + (long)l * G4 * KPH + n0 * KPH;
    const float*  bb = (l == 0) ? b0 : (l == 1) ? b1 : (l == 2) ? b2 : b3;

    float acc[2][8][4];
#pragma unroll
    for (int mi = 0; mi < 2; mi++)
#pragma unroll
        for (int ni = 0; ni < 8; ni++)
#pragma unroll
            for (int k = 0; k < 4; k++) acc[mi][ni][k] = 0.f;

#pragma unroll
    for (int p = 0; p < NSTAGE - 1; p++)
        pre16_issue(sAb + p * PRE_STAGE_BYTES, sBb + p * PRE_STAGE_BYTES,
                    A, Bm, p, tid);

    for (int st = 0; st < PKT; st++) {
        asm volatile("cp.async.wait_group %0;" :: "n"(NSTAGE - 2));
        __syncthreads();
        pre16_compute(s, st & (NSTAGE - 1), acc, wr, wc, g, t4);
        int nk = st + NSTAGE - 1;
        if (nk < PKT)
            pre16_issue(sAb + (nk & (NSTAGE - 1)) * PRE_STAGE_BYTES,
                        sBb + (nk & (NSTAGE - 1)) * PRE_STAGE_BYTES,
                        A, Bm, nk, tid);
        else
            asm volatile("cp.async.commit_group;");
    }

    float* out = g_pre + (long)l * BT * G4;
#pragma unroll
    for (int mi = 0; mi < 2; mi++)
#pragma unroll
        for (int ni = 0; ni < 8; ni++) {
            long col = n0 + wc * 64 + ni * 8 + t4 * 2;
            float bx = bb[col], by = bb[col + 1];
#pragma unroll
            for (int h = 0; h < 2; h++) {
                long row = m0 + wr * 32 + mi * 16 + g + h * 8;
                float2 v;
                v.x = acc[mi][ni][h * 2 + 0] + bx;
                v.y = acc[mi][ni][h * 2 + 1] + by;
                *(float2*)(out + row * G4 + col) = v;
            }
        }
}

// ===========================================================================
// Persistent recurrent kernel (128 blocks, 1/SM, 512 threads) — fp16 GEMM,
// PAIR-PRIVATE PIPELINES: warp pair (2k,2k+1) owns a disjoint 32-row M-strip
// of A and runs its own cp.async pipeline over private stage buffers, synced
// by a per-pair named barrier (bar.sync 1+wr, 64). No block-wide sync in the
// mainloop -> 8 independent instruction streams per SM, no traffic increase.
// ===========================================================================
#define STEP_THREADS 512

struct StepSmem {
    uint2  Wfrag[256][32];             // 64 KB
    __half As[8][NSTAGE][32][72];      // 8 pairs x 4 stages x 4.5 KB = 144 KB
};
#define STEP_SMEM_BYTES sizeof(StepSmem)
#define PAIR_STAGE_BYTES (32 * 72 * 2)

// Issue one K=64 stage for this pair's 32 rows (both warps issue half).
__device__ __forceinline__ void issue_pair(unsigned pair_base_b,
                                           const __half* hp, int s,
                                           int ptid, int wr)
{
#pragma unroll
    for (int i = 0; i < 4; i++) {
        int c = ptid + i * 64;               // 0..255 chunks of 16B
        int row = c >> 3, ch = c & 7;
        unsigned dst = pair_base_b + (unsigned)(row * 72 + ch * 8) * 2u;
        const __half* src = hp + (wr * 32 + row) * 512 + s * 64 + ch * 8;
        asm volatile("cp.async.cg.shared.global [%0], [%1], 16;"
                     :: "r"(dst), "l"(src));
    }
    asm volatile("cp.async.commit_group;");
}

__device__ __forceinline__ void step_compute_stage(
    const StepSmem* s, int wr, int stg, int st, float acc[2][4][4],
    int wc, int g, int t4, int lane)
{
    const __half* As = &s->As[wr][stg][0][0];
#pragma unroll
    for (int ks = 0; ks < 4; ks++) {
        int kh = ks * 16;
        unsigned af[2][4];
        uint2    bf[4];
#pragma unroll
        for (int mi = 0; mi < 2; mi++) {
            int r0 = (mi * 16 + g) * 72;     // pair-local rows
            int r1 = r0 + 8 * 72;
            af[mi][0] = *(const unsigned*)(As + r0 + kh + 2 * t4);
            af[mi][1] = *(const unsigned*)(As + r1 + kh + 2 * t4);
            af[mi][2] = *(const unsigned*)(As + r0 + kh + 8 + 2 * t4);
            af[mi][3] = *(const unsigned*)(As + r1 + kh + 8 + 2 * t4);
        }
        int kt = st * 4 + ks;
#pragma unroll
        for (int ni = 0; ni < 4; ni++)
            bf[ni] = s->Wfrag[kt * 8 + wc * 4 + ni][lane];
#pragma unroll
        for (int mi = 0; mi < 2; mi++)
#pragma unroll
            for (int ni = 0; ni < 4; ni++)
                asm volatile(
                    "mma.sync.aligned.m16n8k16.row.col.f32.f16.f16.f32 "
                    "{%0,%1,%2,%3},{%4,%5,%6,%7},{%8,%9},{%0,%1,%2,%3};"
                    : "+f"(acc[mi][ni][0]), "+f"(acc[mi][ni][1]),
                      "+f"(acc[mi][ni][2]), "+f"(acc[mi][ni][3])
                    : "r"(af[mi][0]), "r"(af[mi][1]), "r"(af[mi][2]), "r"(af[mi][3]),
                      "r"(bf[ni].x), "r"(bf[ni].y));
    }
}

__global__ __launch_bounds__(STEP_THREADS, 1) void k_step_persist()
{
    extern __shared__ char raw[];
    StepSmem* s = (StepSmem*)raw;
    int tid = threadIdx.x, lane = tid & 31, wid = tid >> 5;
    int wr = wid >> 1, wc = wid & 1, g = lane >> 2, t4 = lane & 3;
    int ptid = tid & 63;                     // thread id within pair
    int bar_id = 1 + wr;                     // named barrier per pair
    int bid = blockIdx.x, l = bid >> 5, nb = bid & 31;
    const float* Wh = g_wh + (long)l * H_ * G4;

    // one-time: build fp16 B-fragments in smem (m16n8k16 layout).
    for (int f = wid; f < 256; f += 16) {
        int kt = f >> 3, rest = f & 7, wcf = rest >> 2, ni = rest & 3;
        int col = ni * H_ + nb * 16 + wcf * 8 + g;
        int k0  = kt * 16 + 2 * t4;
        float w0 = Wh[(long)(k0    ) * G4 + col];
        float w1 = Wh[(long)(k0 + 1) * G4 + col];
        float w2 = Wh[(long)(k0 + 8) * G4 + col];
        float w3 = Wh[(long)(k0 + 9) * G4 + col];
        __half2 p0 = __floats2half2_rn(w0, w1);
        __half2 p1 = __floats2half2_rn(w2, w3);
        uint2 v;
        v.x = *(unsigned*)&p0;
        v.y = *(unsigned*)&p1;
        s->Wfrag[f][lane] = v;
    }
    __syncthreads();

    const float* pre_l = g_pre + (long)l * BT * G4;
    unsigned pair0 =
        (unsigned)__cvta_generic_to_shared(&s->As[wr][0][0][0]);
    int u0 = nb * 16 + wc * 8 + t4 * 2;

    float creg[2][2][2];
#pragma unroll
    for (int mi = 0; mi < 2; mi++)
#pragma unroll
        for (int hh = 0; hh < 2; hh++) {
            creg[mi][hh][0] = 0.f;
            creg[mi][hh][1] = 0.f;
        }

    for (int t = 0; t < T_; t++) {
        const __half* hp = g_hh[t & 1] + l * B_ * H_;
        __half* hn = g_hh[(t + 1) & 1] + l * B_ * H_;
        int tl = (l & 1) ? (T_ - 1 - t) : t;

#pragma unroll
        for (int p = 0; p < NSTAGE - 1; p++)
            issue_pair(pair0 + p * PAIR_STAGE_BYTES, hp, p, ptid, wr);

        // prefetch pre values into registers (hidden under the GEMM)
        float2 pr[2][2][4];
#pragma unroll
        for (int mi = 0; mi < 2; mi++)
#pragma unroll
            for (int hh = 0; hh < 2; hh++) {
                int  row = wr * 32 + mi * 16 + g + hh * 8;
                long pb  = ((long)row * T_ + tl) * G4;
#pragma unroll
                for (int gate = 0; gate < 4; gate++)
                    pr[mi][hh][gate] =
                        *(const float2*)(pre_l + pb + gate * H_ + u0);
            }

        float acc[2][4][4];
#pragma unroll
        for (int mi = 0; mi < 2; mi++)
#pragma unroll
            for (int ni = 0; ni < 4; ni++)
#pragma unroll
                for (int k = 0; k < 4; k++) acc[mi][ni][k] = 0.f;

        // pair-private pipeline: per-thread wait + per-pair named barrier
        for (int st = 0; st < KT2; st++) {
            asm volatile("cp.async.wait_group %0;" :: "n"(NSTAGE - 2));
            asm volatile("bar.sync %0, 64;" :: "r"(bar_id) : "memory");
            step_compute_stage(s, wr, st & (NSTAGE - 1), st, acc, wc, g, t4, lane);
            int nk = st + NSTAGE - 1;
            if (nk < KT2)
                issue_pair(pair0 + (nk & (NSTAGE - 1)) * PAIR_STAGE_BYTES,
                           hp, nk, ptid, wr);
            else
                asm volatile("cp.async.commit_group;");
        }

        // epilogue: gates + state update (c in registers, h2 stores)
#pragma unroll
        for (int mi = 0; mi < 2; mi++) {
#pragma unroll
            for (int hh = 0; hh < 2; hh++) {
                int row = wr * 32 + mi * 16 + g + hh * 8;
                float hv[2];
#pragma unroll
                for (int p = 0; p < 2; p++) {
                    int k = hh * 2 + p;
                    float pi = p ? pr[mi][hh][0].y : pr[mi][hh][0].x;
                    float pj = p ? pr[mi][hh][1].y : pr[mi][hh][1].x;
                    float pf = p ? pr[mi][hh][2].y : pr[mi][hh][2].x;
                    float po = p ? pr[mi][hh][3].y : pr[mi][hh][3].x;
                    float zi = acc[mi][0][k] + pi;
                    float zj = acc[mi][1][k] + pj;
                    float zf = acc[mi][2][k] + pf;
                    float zo = acc[mi][3][k] + po;
                    float co = creg[mi][hh][p];
                    float fg = 1.f / (1.f + __expf(-(zf + 1.f)));
                    float ig = 1.f / (1.f + __expf(-zi));
                    float og = 1.f / (1.f + __expf(-zo));
                    float cn = co * fg + ig * tanhf(zj);
                    creg[mi][hh][p] = cn;
                    hv[p] = tanhf(cn) * og;
                }
                *(__half2*)(hn + row * H_ + u0) = __floats2half2_rn(hv[0], hv[1]);
            }
        }

        // per-LSTM software barrier (32 blocks) — proven construct
        __threadfence();
        __syncthreads();
        if (tid == 0) {
            unsigned long long a = atomicAdd(&g_arrive[l], 1ULL) + 1ULL;
            unsigned long long want = (a + 31ULL) >> 5;
            if ((a & 31ULL) == 0ULL) {
                atomicAdd(&g_release[l], 1ULL);
            } else {
                while (*(volatile unsigned long long*)&g_release[l] < want) { }
            }
            __threadfence();
        }
        __syncthreads();
    }

    float* c_l = g_c + l * B_ * H_;
#pragma unroll
    for (int mi = 0; mi < 2; mi++)
#pragma unroll
        for (int hh = 0; hh < 2; hh++) {
            int row = wr * 32 + mi * 16 + g + hh * 8;
            *(float2*)(c_l + row * H_ + u0) =
                make_float2(creg[mi][hh][0], creg[mi][hh][1]);
        }
}

// ===========================================================================
// Tail: gather + MLP (tf32 2-stage GEMM, unchanged)
// ===========================================================================
struct GemmSmem {
    float As[2][128][20];
    float Bs[2][16][136];
};

__device__ __forceinline__ void stage_tiles(
    const float* __restrict__ A, long lda,
    const float* __restrict__ Bm, long ldb,
    int K, long m0, long n0, GemmSmem* s, int buf, int k0)
{
    int tid = threadIdx.x;
    {
        int r = tid >> 2;
        int c = (tid & 3) * 4;
#pragma unroll
        for (int i = 0; i < 2; i++) {
            int row = r + i * 64;
            const float* p = A + (m0 + row) * lda + (k0 + c);
            float4 v;
            if (k0 + c + 3 < K) {
                v = *(const float4*)p;
            } else {
                v.x = (k0 + c + 0 < K) ? p[0] : 0.f;
                v.y = (k0 + c + 1 < K) ? p[1] : 0.f;
                v.z = (k0 + c + 2 < K) ? p[2] : 0.f;
                v.w = (k0 + c + 3 < K) ? p[3] : 0.f;
            }
            s->As[buf][row][c + 0] = f2tf32(v.x);
            s->As[buf][row][c + 1] = f2tf32(v.y);
            s->As[buf][row][c + 2] = f2tf32(v.z);
            s->As[buf][row][c + 3] = f2tf32(v.w);
        }
    }
    {
        int r  = tid >> 4;
        int cb = (tid & 15) * 8;
#pragma unroll
        for (int j = 0; j < 2; j++) {
            int c = cb + j * 4;
            float4 v;
            if (k0 + r < K) {
                v = *(const float4*)(Bm + (long)(k0 + r) * ldb + n0 + c);
            } else {
                v.x = v.y = v.z = v.w = 0.f;
            }
            s->Bs[buf][r][c + 0] = f2tf32(v.x);
            s->Bs[buf][r][c + 1] = f2tf32(v.y);
            s->Bs[buf][r][c + 2] = f2tf32(v.z);
            s->Bs[buf][r][c + 3] = f2tf32(v.w);
        }
    }
}

__device__ __forceinline__ void tf32_compute(
    const float* As, const float* Bs, float acc[4][4][4],
    int wr, int wc, int g, int t4)
{
#pragma unroll
    for (int ks = 0; ks < 2; ks++) {
        int k0 = ks * 8;
        unsigned af[4][4], bf[4][2];
#pragma unroll
        for (int mi = 0; mi < 4; mi++) {
            int rb = wr * 64 + mi * 16;
            af[mi][0] = __float_as_uint(As[(rb + g    ) * 20 + k0 + t4    ]);
            af[mi][1] = __float_as_uint(As[(rb + g + 8) * 20 + k0 + t4    ]);
            af[mi][2] = __float_as_uint(As[(rb + g    ) * 20 + k0 + t4 + 4]);
            af[mi][3] = __float_as_uint(As[(rb + g + 8) * 20 + k0 + t4 + 4]);
        }
#pragma unroll
        for (int ni = 0; ni < 4; ni++) {
            int cb = wc * 32 + ni * 8;
            bf[ni][0] = __float_as_uint(Bs[(k0 + t4    ) * 136 + cb + g]);
            bf[ni][1] = __float_as_uint(Bs[(k0 + t4 + 4) * 136 + cb + g]);
        }
#pragma unroll
        for (int mi = 0; mi < 4; mi++)
#pragma unroll
            for (int ni = 0; ni < 4; ni++)
                asm volatile(
                    "mma.sync.aligned.m16n8k8.row.col.f32.tf32.tf32.f32 "
                    "{%0,%1,%2,%3},{%4,%5,%6,%7},{%8,%9},{%0,%1,%2,%3};"
                    : "+f"(acc[mi][ni][0]), "+f"(acc[mi][ni][1]),
                      "+f"(acc[mi][ni][2]), "+f"(acc[mi][ni][3])
                    : "r"(af[mi][0]), "r"(af[mi][1]), "r"(af[mi][2]), "r"(af[mi][3]),
                      "r"(bf[ni][0]), "r"(bf[ni][1]));
    }
}

__device__ __forceinline__ void gemm_main(
    const float* __restrict__ A, long lda,
    const float* __restrict__ Bm, long ldb,
    int K, long m0, long n0, GemmSmem* s, float acc[4][4][4])
{
    int lane = threadIdx.x & 31, wid = threadIdx.x >> 5;
    int wr = wid >> 2, wc = wid & 3, g = lane >> 2, t4 = lane & 3;
#pragma unroll
    for (int mi = 0; mi < 4; mi++)
#pragma unroll
        for (int ni = 0; ni < 4; ni++)
#pragma unroll
            for (int k = 0; k < 4; k++) acc[mi][ni][k] = 0.f;

    int nkt = (K + 15) >> 4;
    stage_tiles(A, lda, Bm, ldb, K, m0, n0, s, 0, 0);
    __syncthreads();
    for (int kt = 0; kt < nkt; kt++) {
        tf32_compute(&s->As[kt & 1][0][0], &s->Bs[kt & 1][0][0], acc, wr, wc, g, t4);
        if (kt + 1 < nkt)
            stage_tiles(A, lda, Bm, ldb, K, m0, n0, s, (kt + 1) & 1, (kt + 1) * 16);
        __syncthreads();
    }
}

__global__ void k_gather()
{
    int idx = blockIdx.x * 256 + threadIdx.x;
    if (idx < B_ * G4) {
        int b = idx >> 11, kk = idx & 2047;
        int l = kk >> 9, gg = kk & 511;
        g_rnn[idx] = g_c[(long)l * B_ * H_ + (long)b * H_ + gg];
    }
}

__global__ __launch_bounds__(256) void k_dense(
    int a_sel, int K, const float* __restrict__ W, int N,
    const float* __restrict__ bias, int o_sel)
{
    long n0 = (long)blockIdx.x * 128, m0 = (long)blockIdx.y * 128;
    const float* A = (a_sel == 0) ? g_rnn : g_act[a_sel - 1];
    float* out = g_act[o_sel];
    __shared__ GemmSmem s;
    float acc[4][4][4];
    gemm_main(A, (a_sel == 0) ? G4 : F_, W, N, K, m0, n0, &s, acc);

    int lane = threadIdx.x & 31, wid = threadIdx.x >> 5;
    int wr = wid >> 2, wc = wid & 3, g = lane >> 2, t4 = lane & 3;
#pragma unroll
    for (int mi = 0; mi < 4; mi++)
#pragma unroll
        for (int ni = 0; ni < 4; ni++) {
            long col = n0 + wc * 32 + ni * 8 + t4 * 2;
            float bx = bias[col], by = bias[col + 1];
#pragma unroll
            for (int h = 0; h < 2; h++) {
                long row = m0 + wr * 64 + mi * 16 + g + h * 8;
                float2 v;
                v.x = tanhf(acc[mi][ni][h * 2 + 0] + bx);
                v.y = tanhf(acc[mi][ni][h * 2 + 1] + by);
                *(float2*)(out + row * (long)N + col) = v;
            }
        }
}

__global__ void k_logits(const float* __restrict__ W4,
                         const float* __restrict__ b4, float* __restrict__ out)
{
    int b = blockIdx.x, tid = threadIdx.x;
    const float* A = g_act[2] + (long)b * F_;
    float s0 = 0.f, s1 = 0.f, s2 = 0.f;
    for (int k = tid; k < F_; k += 128) {
        float a = A[k];
        s0 += a * W4[k * 3 + 0];
        s1 += a * W4[k * 3 + 1];
        s2 += a * W4[k * 3 + 2];
    }
#pragma unroll
    for (int off = 16; off; off >>= 1) {
        s0 += __shfl_down_sync(0xffffffffu, s0, off);
        s1 += __shfl_down_sync(0xffffffffu, s1, off);
        s2 += __shfl_down_sync(0xffffffffu, s2, off);
    }
    __shared__ float red[3][4];
    if ((tid & 31) == 0) {
        red[0][tid >> 5] = s0; red[1][tid >> 5] = s1; red[2][tid >> 5] = s2;
    }
    __syncthreads();
    if (tid == 0) {
        out[b * 3 + 0] = red[0][0] + red[0][1] + red[0][2] + red[0][3] + b4[0];
        out[b * 3 + 1] = red[1][0] + red[1][1] + red[1][2] + red[1][3] + b4[1];
        out[b * 3 + 2] = red[2][0] + red[2][1] + red[2][2] + red[2][3] + b4[2];
    }
}

// ---------------------------------------------------------------------------
// kernel_launch
// ---------------------------------------------------------------------------
extern "C" void kernel_launch(void* const* d_in, const int* in_sizes, int n_in,
                              void* d_out, int out_size)
{
    (void)in_sizes; (void)n_in; (void)out_size;
    const float* prem   = (const float*)d_in[0];
    const float* hyp    = (const float*)d_in[1];
    const float* W_fw_p = (const float*)d_in[2];
    const float* b_fw_p = (const float*)d_in[3];
    const float* W_bw_p = (const float*)d_in[4];
    const float* b_bw_p = (const float*)d_in[5];
    const float* W_fw_h = (const float*)d_in[6];
    const float* b_fw_h = (const float*)d_in[7];
    const float* W_bw_h = (const float*)d_in[8];
    const float* b_bw_h = (const float*)d_in[9];
    const float* W1 = (const float*)d_in[10];
    const float* b1 = (const float*)d_in[11];
    const float* W2 = (const float*)d_in[12];
    const float* b2 = (const float*)d_in[13];
    const float* W3 = (const float*)d_in[14];
    const float* b3 = (const float*)d_in[15];
    const float* W4 = (const float*)d_in[16];
    const float* b4 = (const float*)d_in[17];
    float* out = (float*)d_out;

    cudaFuncSetAttribute(k_step_persist,
                         cudaFuncAttributeMaxDynamicSharedMemorySize,
                         (int)STEP_SMEM_BYTES);
    cudaFuncSetAttribute(k_precompute16,
                         cudaFuncAttributeMaxDynamicSharedMemorySize,
                         (int)PRE_SMEM_BYTES);

    // Launch order matters for ncu (capture lands on launch index 3 = step).
    int nz = NL * B_ * H_;
    k_zero<<<(nz + 255) / 256, 256>>>();                              // 0

    long nx = 2L * BT * KPH;
    k_prep_all<<<(int)((nx + 255) / 256), 256>>>(
        prem, hyp, W_fw_p, W_bw_p, W_fw_h, W_bw_h);                   // 1

    k_precompute16<<<dim3(16, 256, 4), 256, PRE_SMEM_BYTES>>>(
        b_fw_p, b_bw_p, b_fw_h, b_bw_h);                              // 2

    k_step_persist<<<128, STEP_THREADS, STEP_SMEM_BYTES>>>();         // 3

    k_gather<<<(B_ * G4 + 255) / 256, 256>>>();                       // 4

    k_dense<<<dim3(8, 2), 256>>>(0, G4, W1, F_, b1, 0);               // 5
    k_dense<<<dim3(8, 2), 256>>>(1, F_, W2, F_, b2, 1);               // 6
    k_dense<<<dim3(8, 2), 256>>>(2, F_, W3, F_, b3, 2);               // 7

    k_logits<<<B_, 128>>>(W4, b4, out);                               // 8
}

// round 17
// speedup vs baseline: 1.4339x; 1.0010x over previous
#include <cuda_runtime.h>
#include <cuda_fp16.h>
#include <math.h>

// Problem constants
#define B_  256
#define T_  128
#define E_  300
#define H_  512
#define G4  2048          // 4*H
#define F_  1024
#define NL  4
#define BT  32768         // B*T
#define KPH 320           // E padded to 64 for fp16 precompute
#define PKT 10            // precompute: 10 stages of K=32
#define KT2 8             // recurrent: 8 stages of K=64
#define NSTAGE 4

// ---------------------------------------------------------------------------
// Device scratch (static; no allocations anywhere)
// ---------------------------------------------------------------------------
__device__ __align__(256) __half g_preh[268435456];        // [4][B*T][G4] fp16, 536 MB
__device__ __align__(256) __half g_xh  [2 * BT * KPH];     // fp16 padded inputs
__device__ __align__(256) __half g_wxT [NL * G4 * KPH];    // fp16 Wx transposed [N,K]
__device__ float  g_wh [NL * H_ * G4];        // RAW fp32 recurrent weights
__device__ __align__(256) __half g_hh[2][NL * B_ * H_];    // fp16 hidden ping-pong
__device__ float  g_c  [NL * B_ * H_];        // cell state (final only)
__device__ float  g_rnn[B_ * G4];             // concat of final c's
__device__ float  g_act[3][B_ * F_];          // MLP activations
__device__ unsigned long long g_arrive [NL];
__device__ unsigned long long g_release[NL];

__device__ __forceinline__ float f2tf32(float x) {
    unsigned u;
    asm("cvt.rna.tf32.f32 %0, %1;" : "=r"(u) : "f"(x));
    return __uint_as_float(u);
}

// ===========================================================================
// k_zero: zero initial states (per replay)
// ===========================================================================
__global__ void k_zero()
{
    int idx = blockIdx.x * 256 + threadIdx.x;
    if (idx < NL * B_ * H_) {
        g_hh[0][idx] = __float2half(0.f);
        g_hh[1][idx] = __float2half(0.f);
    }
}

// ===========================================================================
// k_prep_all: fp16 conversion/padding for precompute; raw copy of Wh.
// ===========================================================================
__global__ void k_prep_all(
    const float* __restrict__ prem, const float* __restrict__ hyp,
    const float* __restrict__ W0, const float* __restrict__ W1,
    const float* __restrict__ W2, const float* __restrict__ W3)
{
    long idx = (long)blockIdx.x * 256 + threadIdx.x;

    if (idx < 2L * BT * KPH) {
        int which = (int)(idx / ((long)BT * KPH));
        long rem  = idx - (long)which * BT * KPH;
        int row = (int)(rem / KPH), col = (int)(rem - (long)row * KPH);
        const float* x = which ? hyp : prem;
        g_xh[idx] = (col < E_) ? __float2half_rn(x[(long)row * E_ + col])
                               : __float2half(0.f);
    }
    if (idx < (long)NL * G4 * KPH) {
        int l = (int)(idx / ((long)G4 * KPH));
        long rem = idx - (long)l * G4 * KPH;
        int c = (int)(rem / KPH), k = (int)(rem - (long)c * KPH);
        const float* W = (l == 0) ? W0 : (l == 1) ? W1 : (l == 2) ? W2 : W3;
        g_wxT[idx] = (k < E_) ? __float2half_rn(W[(long)k * G4 + c])
                              : __float2half(0.f);
    }
    if (idx < (long)NL * H_ * G4) {
        int l = (int)(idx / ((long)H_ * G4));
        long rem = idx - (long)l * H_ * G4;
        int r = (int)(rem / G4), c = (int)(rem - (long)r * G4);
        const float* W = (l == 0) ? W0 : (l == 1) ? W1 : (l == 2) ? W2 : W3;
        g_wh[idx] = W[(long)(E_ + r) * G4 + c];
    }
}

// ===========================================================================
// fp16 precompute GEMM: g_preh[l] = fp16(Xh @ WxT^T + b_l)
// (proven round-15 pipeline; epilogue now stores __half2)
// ===========================================================================
struct PreSmem {
    __half As[NSTAGE][128][40];
    __half Bs[NSTAGE][128][40];
};
#define PRE_SMEM_BYTES sizeof(PreSmem)
#define PRE_STAGE_BYTES (128 * 40 * 2)

__device__ __forceinline__ void pre16_issue(
    unsigned sA, unsigned sB, const __half* __restrict__ A,
    const __half* __restrict__ Bm, int s, int tid)
{
#pragma unroll
    for (int i = 0; i < 2; i++) {
        int c = tid + i * 256;
        int row = c >> 2, ch = c & 3;
        unsigned dst = sA + (unsigned)(row * 40 + ch * 8) * 2u;
        const __half* src = A + (long)row * KPH + s * 32 + ch * 8;
        asm volatile("cp.async.cg.shared.global [%0], [%1], 16;"
                     :: "r"(dst), "l"(src));
    }
#pragma unroll
    for (int i = 0; i < 2; i++) {
        int c = tid + i * 256;
        int row = c >> 2, ch = c & 3;
        unsigned dst = sB + (unsigned)(row * 40 + ch * 8) * 2u;
        const __half* src = Bm + (long)row * KPH + s * 32 + ch * 8;
        asm volatile("cp.async.cg.shared.global [%0], [%1], 16;"
                     :: "r"(dst), "l"(src));
    }
    asm volatile("cp.async.commit_group;");
}

__device__ __forceinline__ void pre16_compute(
    const PreSmem* s, int stg, float acc[2][8][4],
    int wr, int wc, int g, int t4)
{
    const __half* As = &s->As[stg][0][0];
    const __half* Bs = &s->Bs[stg][0][0];
#pragma unroll
    for (int ks = 0; ks < 2; ks++) {
        int kh = ks * 16;
        unsigned af[2][4], bf[8][2];
#pragma unroll
        for (int mi = 0; mi < 2; mi++) {
            int r0 = (wr * 32 + mi * 16 + g) * 40;
            int r1 = r0 + 8 * 40;
            af[mi][0] = *(const unsigned*)(As + r0 + kh + 2 * t4);
            af[mi][1] = *(const unsigned*)(As + r1 + kh + 2 * t4);
            af[mi][2] = *(const unsigned*)(As + r0 + kh + 8 + 2 * t4);
            af[mi][3] = *(const unsigned*)(As + r1 + kh + 8 + 2 * t4);
        }
#pragma unroll
        for (int ni = 0; ni < 8; ni++) {
            int rb = (wc * 64 + ni * 8 + g) * 40;
            bf[ni][0] = *(const unsigned*)(Bs + rb + kh + 2 * t4);
            bf[ni][1] = *(const unsigned*)(Bs + rb + kh + 8 + 2 * t4);
        }
#pragma unroll
        for (int mi = 0; mi < 2; mi++)
#pragma unroll
            for (int ni = 0; ni < 8; ni++)
                asm volatile(
                    "mma.sync.aligned.m16n8k16.row.col.f32.f16.f16.f32 "
                    "{%0,%1,%2,%3},{%4,%5,%6,%7},{%8,%9},{%0,%1,%2,%3};"
                    : "+f"(acc[mi][ni][0]), "+f"(acc[mi][ni][1]),
                      "+f"(acc[mi][ni][2]), "+f"(acc[mi][ni][3])
                    : "r"(af[mi][0]), "r"(af[mi][1]), "r"(af[mi][2]), "r"(af[mi][3]),
                      "r"(bf[ni][0]), "r"(bf[ni][1]));
    }
}

__global__ __launch_bounds__(256, 2) void k_precompute16(
    const float* __restrict__ b0, const float* __restrict__ b1,
    const float* __restrict__ b2, const float* __restrict__ b3)
{
    extern __shared__ char raw[];
    PreSmem* s = (PreSmem*)raw;
    unsigned sAb = (unsigned)__cvta_generic_to_shared(&s->As[0][0][0]);
    unsigned sBb = (unsigned)__cvta_generic_to_shared(&s->Bs[0][0][0]);

    int tid = threadIdx.x, lane = tid & 31, wid = tid >> 5;
    int wr = wid >> 1, wc = wid & 1, g = lane >> 2, t4 = lane & 3;
    int l = blockIdx.z;
    long n0 = (long)blockIdx.x * 128, m0 = (long)blockIdx.y * 128;
    const __half* A  = g_xh  + (long)(l >> 1) * BT * KPH + m0 * KPH;
    const __half* Bm = g_wxT + (long)l * G4 * KPH + n0 * KPH;
    const float*  bb = (l == 0) ? b0 : (l == 1) ? b1 : (l == 2) ? b2 : b3;

    float acc[2][8][4];
#pragma unroll
    for (int mi = 0; mi < 2; mi++)
#pragma unroll
        for (int ni = 0; ni < 8; ni++)
#pragma unroll
            for (int k = 0; k < 4; k++) acc[mi][ni][k] = 0.f;

#pragma unroll
    for (int p = 0; p < NSTAGE - 1; p++)
        pre16_issue(sAb + p * PRE_STAGE_BYTES, sBb + p * PRE_STAGE_BYTES,
                    A, Bm, p, tid);

    for (int st = 0; st < PKT; st++) {
        asm volatile("cp.async.wait_group %0;" :: "n"(NSTAGE - 2));
        __syncthreads();
        pre16_compute(s, st & (NSTAGE - 1), acc, wr, wc, g, t4);
        int nk = st + NSTAGE - 1;
        if (nk < PKT)
            pre16_issue(sAb + (nk & (NSTAGE - 1)) * PRE_STAGE_BYTES,
                        sBb + (nk & (NSTAGE - 1)) * PRE_STAGE_BYTES,
                        A, Bm, nk, tid);
        else
            asm volatile("cp.async.commit_group;");
    }

    __half* out = g_preh + (long)l * BT * G4;
#pragma unroll
    for (int mi = 0; mi < 2; mi++)
#pragma unroll
        for (int ni = 0; ni < 8; ni++) {
            long col = n0 + wc * 64 + ni * 8 + t4 * 2;
            float bx = bb[col], by = bb[col + 1];
#pragma unroll
            for (int h = 0; h < 2; h++) {
                long row = m0 + wr * 32 + mi * 16 + g + h * 8;
                *(__half2*)(out + row * G4 + col) =
                    __floats2half2_rn(acc[mi][ni][h * 2 + 0] + bx,
                                      acc[mi][ni][h * 2 + 1] + by);
            }
        }
}

// ===========================================================================
// Persistent recurrent kernel (128 blocks, 1/SM, 512 threads) — fp16 GEMM,
// pair-private pipelines (proven round-16). pre reads now fp16 (half2).
// ===========================================================================
#define STEP_THREADS 512

struct StepSmem {
    uint2  Wfrag[256][32];             // 64 KB
    __half As[8][NSTAGE][32][72];      // 8 pairs x 4 stages x 4.5 KB = 144 KB
};
#define STEP_SMEM_BYTES sizeof(StepSmem)
#define PAIR_STAGE_BYTES (32 * 72 * 2)

__device__ __forceinline__ void issue_pair(unsigned pair_base_b,
                                           const __half* hp, int s,
                                           int ptid, int wr)
{
#pragma unroll
    for (int i = 0; i < 4; i++) {
        int c = ptid + i * 64;               // 0..255 chunks of 16B
        int row = c >> 3, ch = c & 7;
        unsigned dst = pair_base_b + (unsigned)(row * 72 + ch * 8) * 2u;
        const __half* src = hp + (wr * 32 + row) * 512 + s * 64 + ch * 8;
        asm volatile("cp.async.cg.shared.global [%0], [%1], 16;"
                     :: "r"(dst), "l"(src));
    }
    asm volatile("cp.async.commit_group;");
}

__device__ __forceinline__ void step_compute_stage(
    const StepSmem* s, int wr, int stg, int st, float acc[2][4][4],
    int wc, int g, int t4, int lane)
{
    const __half* As = &s->As[wr][stg][0][0];
#pragma unroll
    for (int ks = 0; ks < 4; ks++) {
        int kh = ks * 16;
        unsigned af[2][4];
        uint2    bf[4];
#pragma unroll
        for (int mi = 0; mi < 2; mi++) {
            int r0 = (mi * 16 + g) * 72;
            int r1 = r0 + 8 * 72;
            af[mi][0] = *(const unsigned*)(As + r0 + kh + 2 * t4);
            af[mi][1] = *(const unsigned*)(As + r1 + kh + 2 * t4);
            af[mi][2] = *(const unsigned*)(As + r0 + kh + 8 + 2 * t4);
            af[mi][3] = *(const unsigned*)(As + r1 + kh + 8 + 2 * t4);
        }
        int kt = st * 4 + ks;
#pragma unroll
        for (int ni = 0; ni < 4; ni++)
            bf[ni] = s->Wfrag[kt * 8 + wc * 4 + ni][lane];
#pragma unroll
        for (int mi = 0; mi < 2; mi++)
#pragma unroll
            for (int ni = 0; ni < 4; ni++)
                asm volatile(
                    "mma.sync.aligned.m16n8k16.row.col.f32.f16.f16.f32 "
                    "{%0,%1,%2,%3},{%4,%5,%6,%7},{%8,%9},{%0,%1,%2,%3};"
                    : "+f"(acc[mi][ni][0]), "+f"(acc[mi][ni][1]),
                      "+f"(acc[mi][ni][2]), "+f"(acc[mi][ni][3])
                    : "r"(af[mi][0]), "r"(af[mi][1]), "r"(af[mi][2]), "r"(af[mi][3]),
                      "r"(bf[ni].x), "r"(bf[ni].y));
    }
}

__global__ __launch_bounds__(STEP_THREADS, 1) void k_step_persist()
{
    extern __shared__ char raw[];
    StepSmem* s = (StepSmem*)raw;
    int tid = threadIdx.x, lane = tid & 31, wid = tid >> 5;
    int wr = wid >> 1, wc = wid & 1, g = lane >> 2, t4 = lane & 3;
    int ptid = tid & 63;
    int bar_id = 1 + wr;
    int bid = blockIdx.x, l = bid >> 5, nb = bid & 31;
    const float* Wh = g_wh + (long)l * H_ * G4;

    for (int f = wid; f < 256; f += 16) {
        int kt = f >> 3, rest = f & 7, wcf = rest >> 2, ni = rest & 3;
        int col = ni * H_ + nb * 16 + wcf * 8 + g;
        int k0  = kt * 16 + 2 * t4;
        float w0 = Wh[(long)(k0    ) * G4 + col];
        float w1 = Wh[(long)(k0 + 1) * G4 + col];
        float w2 = Wh[(long)(k0 + 8) * G4 + col];
        float w3 = Wh[(long)(k0 + 9) * G4 + col];
        __half2 p0 = __floats2half2_rn(w0, w1);
        __half2 p1 = __floats2half2_rn(w2, w3);
        uint2 v;
        v.x = *(unsigned*)&p0;
        v.y = *(unsigned*)&p1;
        s->Wfrag[f][lane] = v;
    }
    __syncthreads();

    const __half* pre_l = g_preh + (long)l * BT * G4;
    unsigned pair0 =
        (unsigned)__cvta_generic_to_shared(&s->As[wr][0][0][0]);
    int u0 = nb * 16 + wc * 8 + t4 * 2;

    float creg[2][2][2];
#pragma unroll
    for (int mi = 0; mi < 2; mi++)
#pragma unroll
        for (int hh = 0; hh < 2; hh++) {
            creg[mi][hh][0] = 0.f;
            creg[mi][hh][1] = 0.f;
        }

    for (int t = 0; t < T_; t++) {
        const __half* hp = g_hh[t & 1] + l * B_ * H_;
        __half* hn = g_hh[(t + 1) & 1] + l * B_ * H_;
        int tl = (l & 1) ? (T_ - 1 - t) : t;

#pragma unroll
        for (int p = 0; p < NSTAGE - 1; p++)
            issue_pair(pair0 + p * PAIR_STAGE_BYTES, hp, p, ptid, wr);

        // prefetch pre values (fp16) into registers
        __half2 pr[2][2][4];
#pragma unroll
        for (int mi = 0; mi < 2; mi++)
#pragma unroll
            for (int hh = 0; hh < 2; hh++) {
                int  row = wr * 32 + mi * 16 + g + hh * 8;
                long pb  = ((long)row * T_ + tl) * G4;
#pragma unroll
                for (int gate = 0; gate < 4; gate++)
                    pr[mi][hh][gate] =
                        *(const __half2*)(pre_l + pb + gate * H_ + u0);
            }

        float acc[2][4][4];
#pragma unroll
        for (int mi = 0; mi < 2; mi++)
#pragma unroll
            for (int ni = 0; ni < 4; ni++)
#pragma unroll
                for (int k = 0; k < 4; k++) acc[mi][ni][k] = 0.f;

        for (int st = 0; st < KT2; st++) {
            asm volatile("cp.async.wait_group %0;" :: "n"(NSTAGE - 2));
            asm volatile("bar.sync %0, 64;" :: "r"(bar_id) : "memory");
            step_compute_stage(s, wr, st & (NSTAGE - 1), st, acc, wc, g, t4, lane);
            int nk = st + NSTAGE - 1;
            if (nk < KT2)
                issue_pair(pair0 + (nk & (NSTAGE - 1)) * PAIR_STAGE_BYTES,
                           hp, nk, ptid, wr);
            else
                asm volatile("cp.async.commit_group;");
        }

#pragma unroll
        for (int mi = 0; mi < 2; mi++) {
#pragma unroll
            for (int hh = 0; hh < 2; hh++) {
                int row = wr * 32 + mi * 16 + g + hh * 8;
                float hv[2];
                float2 pi2 = __half22float2(pr[mi][hh][0]);
                float2 pj2 = __half22float2(pr[mi][hh][1]);
                float2 pf2 = __half22float2(pr[mi][hh][2]);
                float2 po2 = __half22float2(pr[mi][hh][3]);
#pragma unroll
                for (int p = 0; p < 2; p++) {
                    int k = hh * 2 + p;
                    float zi = acc[mi][0][k] + (p ? pi2.y : pi2.x);
                    float zj = acc[mi][1][k] + (p ? pj2.y : pj2.x);
                    float zf = acc[mi][2][k] + (p ? pf2.y : pf2.x);
                    float zo = acc[mi][3][k] + (p ? po2.y : po2.x);
                    float co = creg[mi][hh][p];
                    float fg = 1.f / (1.f + __expf(-(zf + 1.f)));
                    float ig = 1.f / (1.f + __expf(-zi));
                    float og = 1.f / (1.f + __expf(-zo));
                    float cn = co * fg + ig * tanhf(zj);
                    creg[mi][hh][p] = cn;
                    hv[p] = tanhf(cn) * og;
                }
                *(__half2*)(hn + row * H_ + u0) = __floats2half2_rn(hv[0], hv[1]);
            }
        }

        // per-LSTM software barrier (32 blocks) — proven construct
        __threadfence();
        __syncthreads();
        if (tid == 0) {
            unsigned long long a = atomicAdd(&g_arrive[l], 1ULL) + 1ULL;
            unsigned long long want = (a + 31ULL) >> 5;
            if ((a & 31ULL) == 0ULL) {
                atomicAdd(&g_release[l], 1ULL);
            } else {
                while (*(volatile unsigned long long*)&g_release[l] < want) { }
            }
            __threadfence();
        }
        __syncthreads();
    }

    float* c_l = g_c + l * B_ * H_;
#pragma unroll
    for (int mi = 0; mi < 2; mi++)
#pragma unroll
        for (int hh = 0; hh < 2; hh++) {
            int row = wr * 32 + mi * 16 + g + hh * 8;
            *(float2*)(c_l + row * H_ + u0) =
                make_float2(creg[mi][hh][0], creg[mi][hh][1]);
        }
}

// ===========================================================================
// Tail: gather + MLP (tf32 2-stage GEMM, unchanged)
// ===========================================================================
struct GemmSmem {
    float As[2][128][20];
    float Bs[2][16][136];
};

__device__ __forceinline__ void stage_tiles(
    const float* __restrict__ A, long lda,
    const float* __restrict__ Bm, long ldb,
    int K, long m0, long n0, GemmSmem* s, int buf, int k0)
{
    int tid = threadIdx.x;
    {
        int r = tid >> 2;
        int c = (tid & 3) * 4;
#pragma unroll
        for (int i = 0; i < 2; i++) {
            int row = r + i * 64;
            const float* p = A + (m0 + row) * lda + (k0 + c);
            float4 v;
            if (k0 + c + 3 < K) {
                v = *(const float4*)p;
            } else {
                v.x = (k0 + c + 0 < K) ? p[0] : 0.f;
                v.y = (k0 + c + 1 < K) ? p[1] : 0.f;
                v.z = (k0 + c + 2 < K) ? p[2] : 0.f;
                v.w = (k0 + c + 3 < K) ? p[3] : 0.f;
            }
            s->As[buf][row][c + 0] = f2tf32(v.x);
            s->As[buf][row][c + 1] = f2tf32(v.y);
            s->As[buf][row][c + 2] = f2tf32(v.z);
            s->As[buf][row][c + 3] = f2tf32(v.w);
        }
    }
    {
        int r  = tid >> 4;
        int cb = (tid & 15) * 8;
#pragma unroll
        for (int j = 0; j < 2; j++) {
            int c = cb + j * 4;
            float4 v;
            if (k0 + r < K) {
                v = *(const float4*)(Bm + (long)(k0 + r) * ldb + n0 + c);
            } else {
                v.x = v.y = v.z = v.w = 0.f;
            }
            s->Bs[buf][r][c + 0] = f2tf32(v.x);
            s->Bs[buf][r][c + 1] = f2tf32(v.y);
            s->Bs[buf][r][c + 2] = f2tf32(v.z);
            s->Bs[buf][r][c + 3] = f2tf32(v.w);
        }
    }
}

__device__ __forceinline__ void tf32_compute(
    const float* As, const float* Bs, float acc[4][4][4],
    int wr, int wc, int g, int t4)
{
#pragma unroll
    for (int ks = 0; ks < 2; ks++) {
        int k0 = ks * 8;
        unsigned af[4][4], bf[4][2];
#pragma unroll
        for (int mi = 0; mi < 4; mi++) {
            int rb = wr * 64 + mi * 16;
            af[mi][0] = __float_as_uint(As[(rb + g    ) * 20 + k0 + t4    ]);
            af[mi][1] = __float_as_uint(As[(rb + g + 8) * 20 + k0 + t4    ]);
            af[mi][2] = __float_as_uint(As[(rb + g    ) * 20 + k0 + t4 + 4]);
            af[mi][3] = __float_as_uint(As[(rb + g + 8) * 20 + k0 + t4 + 4]);
        }
#pragma unroll
        for (int ni = 0; ni < 4; ni++) {
            int cb = wc * 32 + ni * 8;
            bf[ni][0] = __float_as_uint(Bs[(k0 + t4    ) * 136 + cb + g]);
            bf[ni][1] = __float_as_uint(Bs[(k0 + t4 + 4) * 136 + cb + g]);
        }
#pragma unroll
        for (int mi = 0; mi < 4; mi++)
#pragma unroll
            for (int ni = 0; ni < 4; ni++)
                asm volatile(
                    "mma.sync.aligned.m16n8k8.row.col.f32.tf32.tf32.f32 "
                    "{%0,%1,%2,%3},{%4,%5,%6,%7},{%8,%9},{%0,%1,%2,%3};"
                    : "+f"(acc[mi][ni][0]), "+f"(acc[mi][ni][1]),
                      "+f"(acc[mi][ni][2]), "+f"(acc[mi][ni][3])
                    : "r"(af[mi][0]), "r"(af[mi][1]), "r"(af[mi][2]), "r"(af[mi][3]),
                      "r"(bf[ni][0]), "r"(bf[ni][1]));
    }
}

__device__ __forceinline__ void gemm_main(
    const float* __restrict__ A, long lda,
    const float* __restrict__ Bm, long ldb,
    int K, long m0, long n0, GemmSmem* s, float acc[4][4][4])
{
    int lane = threadIdx.x & 31, wid = threadIdx.x >> 5;
    int wr = wid >> 2, wc = wid & 3, g = lane >> 2, t4 = lane & 3;
#pragma unroll
    for (int mi = 0; mi < 4; mi++)
#pragma unroll
        for (int ni = 0; ni < 4; ni++)
#pragma unroll
            for (int k = 0; k < 4; k++) acc[mi][ni][k] = 0.f;

    int nkt = (K + 15) >> 4;
    stage_tiles(A, lda, Bm, ldb, K, m0, n0, s, 0, 0);
    __syncthreads();
    for (int kt = 0; kt < nkt; kt++) {
        tf32_compute(&s->As[kt & 1][0][0], &s->Bs[kt & 1][0][0], acc, wr, wc, g, t4);
        if (kt + 1 < nkt)
            stage_tiles(A, lda, Bm, ldb, K, m0, n0, s, (kt + 1) & 1, (kt + 1) * 16);
        __syncthreads();
    }
}

__global__ void k_gather()
{
    int idx = blockIdx.x * 256 + threadIdx.x;
    if (idx < B_ * G4) {
        int b = idx >> 11, kk = idx & 2047;
        int l = kk >> 9, gg = kk & 511;
        g_rnn[idx] = g_c[(long)l * B_ * H_ + (long)b * H_ + gg];
    }
}

__global__ __launch_bounds__(256) void k_dense(
    int a_sel, int K, const float* __restrict__ W, int N,
    const float* __restrict__ bias, int o_sel)
{
    long n0 = (long)blockIdx.x * 128, m0 = (long)blockIdx.y * 128;
    const float* A = (a_sel == 0) ? g_rnn : g_act[a_sel - 1];
    float* out = g_act[o_sel];
    __shared__ GemmSmem s;
    float acc[4][4][4];
    gemm_main(A, (a_sel == 0) ? G4 : F_, W, N, K, m0, n0, &s, acc);

    int lane = threadIdx.x & 31, wid = threadIdx.x >> 5;
    int wr = wid >> 2, wc = wid & 3, g = lane >> 2, t4 = lane & 3;
#pragma unroll
    for (int mi = 0; mi < 4; mi++)
#pragma unroll
        for (int ni = 0; ni < 4; ni++) {
            long col = n0 + wc * 32 + ni * 8 + t4 * 2;
            float bx = bias[col], by = bias[col + 1];
#pragma unroll
            for (int h = 0; h < 2; h++) {
                long row = m0 + wr * 64 + mi * 16 + g + h * 8;
                float2 v;
                v.x = tanhf(acc[mi][ni][h * 2 + 0] + bx);
                v.y = tanhf(acc[mi][ni][h * 2 + 1] + by);
                *(float2*)(out + row * (long)N + col) = v;
            }
        }
}

__global__ void k_logits(const float* __restrict__ W4,
                         const float* __restrict__ b4, float* __restrict__ out)
{
    int b = blockIdx.x, tid = threadIdx.x;
    const float* A = g_act[2] + (long)b * F_;
    float s0 = 0.f, s1 = 0.f, s2 = 0.f;
    for (int k = tid; k < F_; k += 128) {
        float a = A[k];
        s0 += a * W4[k * 3 + 0];
        s1 += a * W4[k * 3 + 1];
        s2 += a * W4[k * 3 + 2];
    }
#pragma unroll
    for (int off = 16; off; off >>= 1) {
        s0 += __shfl_down_sync(0xffffffffu, s0, off);
        s1 += __shfl_down_sync(0xffffffffu, s1, off);
        s2 += __shfl_down_sync(0xffffffffu, s2, off);
    }
    __shared__ float red[3][4];
    if ((tid & 31) == 0) {
        red[0][tid >> 5] = s0; red[1][tid >> 5] = s1; red[2][tid >> 5] = s2;
    }
    __syncthreads();
    if (tid == 0) {
        out[b * 3 + 0] = red[0][0] + red[0][1] + red[0][2] + red[0][3] + b4[0];
        out[b * 3 + 1] = red[1][0] + red[1][1] + red[1][2] + red[1][3] + b4[1];
        out[b * 3 + 2] = red[2][0] + red[2][1] + red[2][2] + red[2][3] + b4[2];
    }
}

// ---------------------------------------------------------------------------
// kernel_launch
// ---------------------------------------------------------------------------
extern "C" void kernel_launch(void* const* d_in, const int* in_sizes, int n_in,
                              void* d_out, int out_size)
{
    (void)in_sizes; (void)n_in; (void)out_size;
    const float* prem   = (const float*)d_in[0];
    const float* hyp    = (const float*)d_in[1];
    const float* W_fw_p = (const float*)d_in[2];
    const float* b_fw_p = (const float*)d_in[3];
    const float* W_bw_p = (const float*)d_in[4];
    const float* b_bw_p = (const float*)d_in[5];
    const float* W_fw_h = (const float*)d_in[6];
    const float* b_fw_h = (const float*)d_in[7];
    const float* W_bw_h = (const float*)d_in[8];
    const float* b_bw_h = (const float*)d_in[9];
    const float* W1 = (const float*)d_in[10];
    const float* b1 = (const float*)d_in[11];
    const float* W2 = (const float*)d_in[12];
    const float* b2 = (const float*)d_in[13];
    const float* W3 = (const float*)d_in[14];
    const float* b3 = (const float*)d_in[15];
    const float* W4 = (const float*)d_in[16];
    const float* b4 = (const float*)d_in[17];
    float* out = (float*)d_out;

    cudaFuncSetAttribute(k_step_persist,
                         cudaFuncAttributeMaxDynamicSharedMemorySize,
                         (int)STEP_SMEM_BYTES);
    cudaFuncSetAttribute(k_precompute16,
                         cudaFuncAttributeMaxDynamicSharedMemorySize,
                         (int)PRE_SMEM_BYTES);

    // Launch order matters for ncu (capture lands on launch index 3 = step).
    int nz = NL * B_ * H_;
    k_zero<<<(nz + 255) / 256, 256>>>();                              // 0

    long nx = 2L * BT * KPH;
    k_prep_all<<<(int)((nx + 255) / 256), 256>>>(
        prem, hyp, W_fw_p, W_bw_p, W_fw_h, W_bw_h);                   // 1

    k_precompute16<<<dim3(16, 256, 4), 256, PRE_SMEM_BYTES>>>(
        b_fw_p, b_bw_p, b_fw_h, b_bw_h);                              // 2

    k_step_persist<<<128, STEP_THREADS, STEP_SMEM_BYTES>>>();         // 3

    k_gather<<<(B_ * G4 + 255) / 256, 256>>>();                       // 4

    k_dense<<<dim3(8, 2), 256>>>(0, G4, W1, F_, b1, 0);               // 5
    k_dense<<<dim3(8, 2), 256>>>(1, F_, W2, F_, b2, 1);               // 6
    k_dense<<<dim3(8, 2), 256>>>(2, F_, W3, F_, b3, 2);               // 7

    k_logits<<<B_, 128>>>(W4, b4, out);                               // 8
}